// round 1
// baseline (speedup 1.0000x reference)
#include <cuda_runtime.h>
#include <cstdint>
#include <math_constants.h>

#define BATCH   16384
#define S       2048
#define G       256
#define NT      256
#define EPT     (S / NT)   // 8

// ---- order-preserving float<->uint transforms ----
__device__ __forceinline__ uint32_t f2u(float f) {
    uint32_t b = __float_as_uint(f);
    return b ^ ((b & 0x80000000u) ? 0xFFFFFFFFu : 0x80000000u);
}
__device__ __forceinline__ float u2f(uint32_t u) {
    uint32_t b = (u & 0x80000000u) ? (u ^ 0x80000000u) : ~u;
    return __uint_as_float(b);
}

// ---- block reductions (256 threads = 8 warps) ----
__device__ __forceinline__ float block_max(float v, float* s) {
#pragma unroll
    for (int o = 16; o; o >>= 1) v = fmaxf(v, __shfl_xor_sync(0xffffffffu, v, o));
    int w = threadIdx.x >> 5;
    if ((threadIdx.x & 31) == 0) s[w] = v;
    __syncthreads();
    if (threadIdx.x < 32) {
        float t = (threadIdx.x < 8) ? s[threadIdx.x] : -CUDART_INF_F;
#pragma unroll
        for (int o = 4; o; o >>= 1) t = fmaxf(t, __shfl_xor_sync(0xffffffffu, t, o));
        if (threadIdx.x == 0) s[0] = t;
    }
    __syncthreads();
    float r = s[0];
    __syncthreads();
    return r;
}

__device__ __forceinline__ float block_sum_f(float v, float* s) {
#pragma unroll
    for (int o = 16; o; o >>= 1) v += __shfl_xor_sync(0xffffffffu, v, o);
    int w = threadIdx.x >> 5;
    if ((threadIdx.x & 31) == 0) s[w] = v;
    __syncthreads();
    if (threadIdx.x < 32) {
        float t = (threadIdx.x < 8) ? s[threadIdx.x] : 0.0f;
#pragma unroll
        for (int o = 4; o; o >>= 1) t += __shfl_xor_sync(0xffffffffu, t, o);
        if (threadIdx.x == 0) s[0] = t;
    }
    __syncthreads();
    float r = s[0];
    __syncthreads();
    return r;
}

__device__ __forceinline__ unsigned long long block_sum_u64(unsigned long long v,
                                                            unsigned long long* s) {
#pragma unroll
    for (int o = 16; o; o >>= 1) v += __shfl_xor_sync(0xffffffffu, v, o);
    int w = threadIdx.x >> 5;
    if ((threadIdx.x & 31) == 0) s[w] = v;
    __syncthreads();
    if (threadIdx.x < 32) {
        unsigned long long t = (threadIdx.x < 8) ? s[threadIdx.x] : 0ull;
#pragma unroll
        for (int o = 4; o; o >>= 1) t += __shfl_xor_sync(0xffffffffu, t, o);
        if (threadIdx.x == 0) s[0] = t;
    }
    __syncthreads();
    unsigned long long r = s[0];
    __syncthreads();
    return r;
}

// ---- radix select: value with ascending rank r (1-based) among S keys in smem ----
__device__ uint32_t radix_select(const uint32_t* __restrict__ su, uint32_t r,
                                 uint32_t* hist, uint32_t* sh_pair) {
    uint32_t prefix = 0;
    for (int pass = 0; pass < 4; pass++) {
        const int shift = 24 - 8 * pass;
        hist[threadIdx.x] = 0;
        __syncthreads();
#pragma unroll
        for (int k = 0; k < EPT; k++) {
            uint32_t u = su[threadIdx.x + k * NT];
            bool ok = (pass == 0) || ((u >> (shift + 8)) == prefix);
            if (ok) atomicAdd(&hist[(u >> shift) & 0xFFu], 1u);
        }
        __syncthreads();
        // Hillis-Steele inclusive scan over 256 bins
#pragma unroll
        for (int off = 1; off < NT; off <<= 1) {
            uint32_t x = hist[threadIdx.x];
            uint32_t y = (threadIdx.x >= (uint32_t)off) ? hist[threadIdx.x - off] : 0u;
            __syncthreads();
            hist[threadIdx.x] = x + y;
            __syncthreads();
        }
        uint32_t inc = hist[threadIdx.x];
        uint32_t exc = threadIdx.x ? hist[threadIdx.x - 1] : 0u;
        if (exc < r && r <= inc) {
            sh_pair[0] = threadIdx.x;
            sh_pair[1] = r - exc;
        }
        __syncthreads();
        prefix = (prefix << 8) | sh_pair[0];
        r = sh_pair[1];
        __syncthreads();
    }
    return prefix;
}

__global__ __launch_bounds__(NT)
void portfolio_kernel(const float* __restrict__ scores,
                      const float* __restrict__ short_ratio,
                      float* __restrict__ out) {
    const int row = blockIdx.x;
    const int tid = threadIdx.x;

    __shared__ uint32_t su[S];
    __shared__ uint32_t hist[NT];
    __shared__ uint32_t sh_pair[2];
    __shared__ float sredf[8];
    __shared__ unsigned long long sredu[8];

    // ---- load row, transform to orderable uints, track max/min ----
    const float4* rowp = reinterpret_cast<const float4*>(scores + (size_t)row * S);
    float lmax = -CUDART_INF_F, lmin = CUDART_INF_F;
#pragma unroll
    for (int k = 0; k < 2; k++) {
        float4 v = rowp[tid + k * NT];
        int j = (tid + k * NT) * 4;
        su[j + 0] = f2u(v.x);
        su[j + 1] = f2u(v.y);
        su[j + 2] = f2u(v.z);
        su[j + 3] = f2u(v.w);
        lmax = fmaxf(lmax, fmaxf(fmaxf(v.x, v.y), fmaxf(v.z, v.w)));
        lmin = fminf(lmin, fminf(fminf(v.x, v.y), fminf(v.z, v.w)));
    }
    __syncthreads();

    const float maxF = block_max(lmax, sredf);
    const float minF = -block_max(-lmin, sredf);

    // ---- thresholds: 256th largest (rank S-G+1 asc), 256th smallest (rank G asc) ----
    const uint32_t uw = radix_select(su, (uint32_t)(S - G + 1), hist, sh_pair);
    const uint32_t ul = radix_select(su, (uint32_t)G, hist, sh_pair);
    const float sw_val = u2f(uw);
    const float sl_val = u2f(ul);

    // ---- counts + exp-sums for strict winners/losers ----
    uint32_t cWgt = 0, cWeq = 0, cLlt = 0, cLeq = 0;
    float sW = 0.0f, sL = 0.0f;
#pragma unroll
    for (int k = 0; k < EPT; k++) {
        uint32_t u = su[tid + k * NT];
        float s = u2f(u);
        if (u > uw) { cWgt++; sW += __expf(s - maxF); }
        else if (u == uw) { cWeq++; }
        if (u < ul) { cLlt++; sL += __expf(minF - s); }
        else if (u == ul) { cLeq++; }
    }
    unsigned long long packed =
        (unsigned long long)cWgt | ((unsigned long long)cWeq << 16) |
        ((unsigned long long)cLlt << 32) | ((unsigned long long)cLeq << 48);
    packed = block_sum_u64(packed, sredu);
    const int nWgt = (int)(packed & 0xFFFFu);
    const int nWeq = (int)((packed >> 16) & 0xFFFFu);
    const int nLlt = (int)((packed >> 32) & 0xFFFFu);
    const int nLeq = (int)((packed >> 48) & 0xFFFFu);

    const int eW = G - nWgt;   // equals-at-threshold to include (>=1)
    const int eL = G - nLlt;

    sW = block_sum_f(sW, sredf);
    sL = block_sum_f(sL, sredf);

    const float expWeq = __expf(sw_val - maxF);
    const float expLeq = __expf(minF - sl_val);
    const float invW = 1.0f / (sW + (float)eW * expWeq);
    const float invL = 1.0f / (sL + (float)eL * expLeq);
    const float wEq = expWeq * invW;
    const float lEq = expLeq * invL;

    // ---- write both weight planes, coalesced float4 ----
    float4* outL = reinterpret_cast<float4*>(out + (size_t)row * S);
    float4* outSh = reinterpret_cast<float4*>(out + (size_t)BATCH * S + (size_t)row * S);
#pragma unroll
    for (int k = 0; k < 2; k++) {
        int q = tid + k * NT;      // float4 slot
        int base = q * 4;
        float lw[4], sw4[4];
#pragma unroll
        for (int c = 0; c < 4; c++) {
            int j = base + c;
            uint32_t u = su[j];
            float s = u2f(u);
            float lval = 0.0f, sval = 0.0f;
            if (u > uw) {
                lval = __expf(s - maxF) * invW;
            } else if (u == uw) {
                if (nWeq == eW) {
                    lval = wEq;
                } else {  // rare boundary tie: rank among equals by index
                    int before = 0;
                    for (int m = 0; m < j; m++) before += (su[m] == uw);
                    if (before < eW) lval = wEq;
                }
            }
            if (u < ul) {
                sval = __expf(minF - s) * invL;
            } else if (u == ul) {
                if (nLeq == eL) {
                    sval = lEq;
                } else {
                    int before = 0;
                    for (int m = 0; m < j; m++) before += (su[m] == ul);
                    if (before < eL) sval = lEq;
                }
            }
            lw[c] = lval;
            sw4[c] = sval;
        }
        outL[q]  = make_float4(lw[0], lw[1], lw[2], lw[3]);
        outSh[q] = make_float4(sw4[0], sw4[1], sw4[2], sw4[3]);
    }

    // ---- short_ratio passthrough (clipped) ----
    if (tid == 0) {
        float r = short_ratio[row];
        r = fminf(fmaxf(r, 0.0f), 1.0f);
        out[(size_t)2 * BATCH * S + row] = r;
    }
}

extern "C" void kernel_launch(void* const* d_in, const int* in_sizes, int n_in,
                              void* d_out, int out_size) {
    const float* scores = (const float*)d_in[0];
    const float* ratio  = (const float*)d_in[1];
    // defensive: identify by size (scores is BATCH*S, ratio is BATCH)
    if (n_in >= 2 && in_sizes[0] == BATCH && in_sizes[1] == BATCH * S) {
        const float* t = scores; scores = ratio; ratio = t;
    }
    portfolio_kernel<<<BATCH, NT>>>(scores, ratio, (float*)d_out);
}

// round 2
// speedup vs baseline: 1.0604x; 1.0604x over previous
#include <cuda_runtime.h>
#include <cstdint>
#include <math_constants.h>

#define BATCH   16384
#define S       2048
#define G       256
#define NT      256
#define EPT     (S / NT)   // 8

// ---- order-preserving float<->uint transforms ----
__device__ __forceinline__ uint32_t f2u(float f) {
    uint32_t b = __float_as_uint(f);
    return b ^ ((b & 0x80000000u) ? 0xFFFFFFFFu : 0x80000000u);
}
__device__ __forceinline__ float u2f(uint32_t u) {
    uint32_t b = (u & 0x80000000u) ? (u ^ 0x80000000u) : ~u;
    return __uint_as_float(b);
}

// ---- block reductions (256 threads = 8 warps) ----
__device__ __forceinline__ float block_max(float v, float* s) {
#pragma unroll
    for (int o = 16; o; o >>= 1) v = fmaxf(v, __shfl_xor_sync(0xffffffffu, v, o));
    int w = threadIdx.x >> 5;
    if ((threadIdx.x & 31) == 0) s[w] = v;
    __syncthreads();
    if (threadIdx.x < 32) {
        float t = (threadIdx.x < 8) ? s[threadIdx.x] : -CUDART_INF_F;
#pragma unroll
        for (int o = 4; o; o >>= 1) t = fmaxf(t, __shfl_xor_sync(0xffffffffu, t, o));
        if (threadIdx.x == 0) s[0] = t;
    }
    __syncthreads();
    float r = s[0];
    __syncthreads();
    return r;
}

__device__ __forceinline__ float block_sum_f(float v, float* s) {
#pragma unroll
    for (int o = 16; o; o >>= 1) v += __shfl_xor_sync(0xffffffffu, v, o);
    int w = threadIdx.x >> 5;
    if ((threadIdx.x & 31) == 0) s[w] = v;
    __syncthreads();
    if (threadIdx.x < 32) {
        float t = (threadIdx.x < 8) ? s[threadIdx.x] : 0.0f;
#pragma unroll
        for (int o = 4; o; o >>= 1) t += __shfl_xor_sync(0xffffffffu, t, o);
        if (threadIdx.x == 0) s[0] = t;
    }
    __syncthreads();
    float r = s[0];
    __syncthreads();
    return r;
}

__device__ __forceinline__ unsigned long long block_sum_u64(unsigned long long v,
                                                            unsigned long long* s) {
#pragma unroll
    for (int o = 16; o; o >>= 1) v += __shfl_xor_sync(0xffffffffu, v, o);
    int w = threadIdx.x >> 5;
    if ((threadIdx.x & 31) == 0) s[w] = v;
    __syncthreads();
    if (threadIdx.x < 32) {
        unsigned long long t = (threadIdx.x < 8) ? s[threadIdx.x] : 0ull;
#pragma unroll
        for (int o = 4; o; o >>= 1) t += __shfl_xor_sync(0xffffffffu, t, o);
        if (threadIdx.x == 0) s[0] = t;
    }
    __syncthreads();
    unsigned long long r = s[0];
    __syncthreads();
    return r;
}

// ---- block exclusive scan of a packed u64 (two independent u32 lanes) ----
// Values per half stay < 2^32 cumulative (max 2048), so no cross-half carry.
__device__ __forceinline__ unsigned long long block_exscan_u64(unsigned long long v,
                                                               unsigned long long* stot) {
    const uint32_t full = 0xffffffffu;
    int lane = threadIdx.x & 31, w = threadIdx.x >> 5;
    unsigned long long inc = v;
#pragma unroll
    for (int o = 1; o < 32; o <<= 1) {
        unsigned long long t = __shfl_up_sync(full, inc, o);
        if (lane >= o) inc += t;
    }
    if (lane == 31) stot[w] = inc;
    __syncthreads();
    if (threadIdx.x < 32) {
        unsigned long long t = (lane < 8) ? stot[lane] : 0ull;
        unsigned long long it = t;
#pragma unroll
        for (int o = 1; o < 8; o <<= 1) {
            unsigned long long x = __shfl_up_sync(full, it, o);
            if (lane >= o) it += x;
        }
        if (lane < 8) stot[lane] = it - t;  // exclusive warp offsets
    }
    __syncthreads();
    unsigned long long r = (inc - v) + stot[w];
    __syncthreads();   // protect stot reuse across calls
    return r;
}

__global__ __launch_bounds__(NT)
void portfolio_kernel(const float* __restrict__ scores,
                      const float* __restrict__ short_ratio,
                      float* __restrict__ out) {
    const int row = blockIdx.x;
    const int tid = threadIdx.x;

    __shared__ uint32_t su[S];           // 8 KB: row keys
    __shared__ uint32_t hA[2048];        // 8 KB
    __shared__ uint32_t hB[2048];        // 8 KB
    __shared__ unsigned long long stot[8];
    __shared__ uint32_t shres[4];        // binW, rW', binL, rL'
    __shared__ float sredf[8];
    __shared__ unsigned long long sredu[8];

    // ---- load row, transform to orderable uints, track max/min ----
    const float4* rowp = reinterpret_cast<const float4*>(scores + (size_t)row * S);
    float lmax = -CUDART_INF_F, lmin = CUDART_INF_F;
#pragma unroll
    for (int k = 0; k < 2; k++) {
        float4 v = rowp[tid + k * NT];
        int j = (tid + k * NT) * 4;
        su[j + 0] = f2u(v.x);
        su[j + 1] = f2u(v.y);
        su[j + 2] = f2u(v.z);
        su[j + 3] = f2u(v.w);
        lmax = fmaxf(lmax, fmaxf(fmaxf(v.x, v.y), fmaxf(v.z, v.w)));
        lmin = fminf(lmin, fminf(fminf(v.x, v.y), fminf(v.z, v.w)));
    }
    // clear pass-1 histogram while waiting on loads of other threads
#pragma unroll
    for (int k = 0; k < 8; k++) hA[tid + k * NT] = 0;
    __syncthreads();

    const float maxF = block_max(lmax, sredf);
    const float minF = -block_max(-lmin, sredf);

    // =========================================================================
    // Fused 3-pass radix select (digits 11/11/10) for BOTH thresholds:
    //   winner threshold: ascending rank S-G+1 = 1793
    //   loser  threshold: ascending rank G     = 256
    // =========================================================================
    uint32_t rW = (uint32_t)(S - G + 1);
    uint32_t rL = (uint32_t)G;

    // ---- pass 1: top 11 bits, single shared histogram ----
#pragma unroll
    for (int k = 0; k < EPT; k++) atomicAdd(&hA[su[tid + k * NT] >> 21], 1u);
    __syncthreads();
    {
        uint32_t c[8], sum = 0;
#pragma unroll
        for (int k = 0; k < 8; k++) { c[k] = hA[tid * 8 + k]; sum += c[k]; }
        unsigned long long e = block_exscan_u64((unsigned long long)sum, stot);
        uint32_t exc = (uint32_t)e;
        if (exc < rW && rW <= exc + sum) {
            uint32_t run = exc;
#pragma unroll
            for (int k = 0; k < 8; k++) {
                if (rW > run && rW <= run + c[k]) { shres[0] = tid * 8 + k; shres[1] = rW - run; }
                run += c[k];
            }
        }
        if (exc < rL && rL <= exc + sum) {
            uint32_t run = exc;
#pragma unroll
            for (int k = 0; k < 8; k++) {
                if (rL > run && rL <= run + c[k]) { shres[2] = tid * 8 + k; shres[3] = rL - run; }
                run += c[k];
            }
        }
        __syncthreads();
    }
    const uint32_t pW1 = shres[0]; rW = shres[1];
    const uint32_t pL1 = shres[2]; rL = shres[3];
    __syncthreads();

    // ---- pass 2: middle 11 bits, two histograms, one packed scan ----
#pragma unroll
    for (int k = 0; k < 8; k++) { hA[tid + k * NT] = 0; hB[tid + k * NT] = 0; }
    __syncthreads();
#pragma unroll
    for (int k = 0; k < EPT; k++) {
        uint32_t u = su[tid + k * NT];
        uint32_t hi = u >> 21;
        if (hi == pW1) atomicAdd(&hA[(u >> 10) & 0x7FFu], 1u);
        if (hi == pL1) atomicAdd(&hB[(u >> 10) & 0x7FFu], 1u);
    }
    __syncthreads();
    {
        uint32_t ca[8], cb[8], sa = 0, sb = 0;
#pragma unroll
        for (int k = 0; k < 8; k++) {
            ca[k] = hA[tid * 8 + k]; sa += ca[k];
            cb[k] = hB[tid * 8 + k]; sb += cb[k];
        }
        unsigned long long e =
            block_exscan_u64((unsigned long long)sa | ((unsigned long long)sb << 32), stot);
        uint32_t ea = (uint32_t)e, eb = (uint32_t)(e >> 32);
        if (ea < rW && rW <= ea + sa) {
            uint32_t run = ea;
#pragma unroll
            for (int k = 0; k < 8; k++) {
                if (rW > run && rW <= run + ca[k]) { shres[0] = tid * 8 + k; shres[1] = rW - run; }
                run += ca[k];
            }
        }
        if (eb < rL && rL <= eb + sb) {
            uint32_t run = eb;
#pragma unroll
            for (int k = 0; k < 8; k++) {
                if (rL > run && rL <= run + cb[k]) { shres[2] = tid * 8 + k; shres[3] = rL - run; }
                run += cb[k];
            }
        }
        __syncthreads();
    }
    const uint32_t pfxW = (pW1 << 11) | shres[0]; rW = shres[1];
    const uint32_t pfxL = (pL1 << 11) | shres[2]; rL = shres[3];
    __syncthreads();

    // ---- pass 3: low 10 bits, 1024 bins each ----
#pragma unroll
    for (int k = 0; k < 4; k++) { hA[tid + k * NT] = 0; hB[tid + k * NT] = 0; }
    __syncthreads();
#pragma unroll
    for (int k = 0; k < EPT; k++) {
        uint32_t u = su[tid + k * NT];
        uint32_t hi = u >> 10;
        if (hi == pfxW) atomicAdd(&hA[u & 0x3FFu], 1u);
        if (hi == pfxL) atomicAdd(&hB[u & 0x3FFu], 1u);
    }
    __syncthreads();
    {
        uint32_t ca[4], cb[4], sa = 0, sb = 0;
#pragma unroll
        for (int k = 0; k < 4; k++) {
            ca[k] = hA[tid * 4 + k]; sa += ca[k];
            cb[k] = hB[tid * 4 + k]; sb += cb[k];
        }
        unsigned long long e =
            block_exscan_u64((unsigned long long)sa | ((unsigned long long)sb << 32), stot);
        uint32_t ea = (uint32_t)e, eb = (uint32_t)(e >> 32);
        if (ea < rW && rW <= ea + sa) {
            uint32_t run = ea;
#pragma unroll
            for (int k = 0; k < 4; k++) {
                if (rW > run && rW <= run + ca[k]) shres[0] = tid * 4 + k;
                run += ca[k];
            }
        }
        if (eb < rL && rL <= eb + sb) {
            uint32_t run = eb;
#pragma unroll
            for (int k = 0; k < 4; k++) {
                if (rL > run && rL <= run + cb[k]) shres[2] = tid * 4 + k;
                run += cb[k];
            }
        }
        __syncthreads();
    }
    const uint32_t uw = (pfxW << 10) | shres[0];
    const uint32_t ul = (pfxL << 10) | shres[2];
    __syncthreads();

    const float sw_val = u2f(uw);
    const float sl_val = u2f(ul);

    // ---- counts + exp-sums for strict winners/losers ----
    uint32_t cWgt = 0, cWeq = 0, cLlt = 0, cLeq = 0;
    float sW = 0.0f, sL = 0.0f;
#pragma unroll
    for (int k = 0; k < EPT; k++) {
        uint32_t u = su[tid + k * NT];
        float s = u2f(u);
        if (u > uw) { cWgt++; sW += __expf(s - maxF); }
        else if (u == uw) { cWeq++; }
        if (u < ul) { cLlt++; sL += __expf(minF - s); }
        else if (u == ul) { cLeq++; }
    }
    unsigned long long packed =
        (unsigned long long)cWgt | ((unsigned long long)cWeq << 16) |
        ((unsigned long long)cLlt << 32) | ((unsigned long long)cLeq << 48);
    packed = block_sum_u64(packed, sredu);
    const int nWgt = (int)(packed & 0xFFFFu);
    const int nWeq = (int)((packed >> 16) & 0xFFFFu);
    const int nLlt = (int)((packed >> 32) & 0xFFFFu);
    const int nLeq = (int)((packed >> 48) & 0xFFFFu);

    const int eW = G - nWgt;   // equals-at-threshold to include (>=1)
    const int eL = G - nLlt;

    sW = block_sum_f(sW, sredf);
    sL = block_sum_f(sL, sredf);

    const float expWeq = __expf(sw_val - maxF);
    const float expLeq = __expf(minF - sl_val);
    const float invW = 1.0f / (sW + (float)eW * expWeq);
    const float invL = 1.0f / (sL + (float)eL * expLeq);
    const float wEq = expWeq * invW;
    const float lEq = expLeq * invL;

    // ---- write both weight planes, coalesced float4 ----
    float4* outL = reinterpret_cast<float4*>(out + (size_t)row * S);
    float4* outSh = reinterpret_cast<float4*>(out + (size_t)BATCH * S + (size_t)row * S);
#pragma unroll
    for (int k = 0; k < 2; k++) {
        int q = tid + k * NT;      // float4 slot
        int base = q * 4;
        float lw[4], sw4[4];
#pragma unroll
        for (int c = 0; c < 4; c++) {
            int j = base + c;
            uint32_t u = su[j];
            float s = u2f(u);
            float lval = 0.0f, sval = 0.0f;
            if (u > uw) {
                lval = __expf(s - maxF) * invW;
            } else if (u == uw) {
                if (nWeq == eW) {
                    lval = wEq;
                } else {  // rare boundary tie: rank among equals by index
                    int before = 0;
                    for (int m = 0; m < j; m++) before += (su[m] == uw);
                    if (before < eW) lval = wEq;
                }
            }
            if (u < ul) {
                sval = __expf(minF - s) * invL;
            } else if (u == ul) {
                if (nLeq == eL) {
                    sval = lEq;
                } else {
                    int before = 0;
                    for (int m = 0; m < j; m++) before += (su[m] == ul);
                    if (before < eL) sval = lEq;
                }
            }
            lw[c] = lval;
            sw4[c] = sval;
        }
        outL[q]  = make_float4(lw[0], lw[1], lw[2], lw[3]);
        outSh[q] = make_float4(sw4[0], sw4[1], sw4[2], sw4[3]);
    }

    // ---- short_ratio passthrough (clipped) ----
    if (tid == 0) {
        float r = short_ratio[row];
        r = fminf(fmaxf(r, 0.0f), 1.0f);
        out[(size_t)2 * BATCH * S + row] = r;
    }
}

extern "C" void kernel_launch(void* const* d_in, const int* in_sizes, int n_in,
                              void* d_out, int out_size) {
    const float* scores = (const float*)d_in[0];
    const float* ratio  = (const float*)d_in[1];
    // defensive: identify by size (scores is BATCH*S, ratio is BATCH)
    if (n_in >= 2 && in_sizes[0] == BATCH && in_sizes[1] == BATCH * S) {
        const float* t = scores; scores = ratio; ratio = t;
    }
    portfolio_kernel<<<BATCH, NT>>>(scores, ratio, (float*)d_out);
}

// round 3
// speedup vs baseline: 1.1330x; 1.0685x over previous
#include <cuda_runtime.h>
#include <cstdint>
#include <math_constants.h>

#define BATCH   16384
#define S       2048
#define G       256
#define NT      256
#define EPT     (S / NT)   // 8

// ---- order-preserving float<->uint transforms ----
__device__ __forceinline__ uint32_t f2u(float f) {
    uint32_t b = __float_as_uint(f);
    return b ^ ((b & 0x80000000u) ? 0xFFFFFFFFu : 0x80000000u);
}
__device__ __forceinline__ float u2f(uint32_t u) {
    uint32_t b = (u & 0x80000000u) ? (u ^ 0x80000000u) : ~u;
    return __uint_as_float(b);
}

// ---- fused block sum of two floats (256 threads = 8 warps) ----
__device__ __forceinline__ void block_sum2_f(float& a, float& b, float* s) {
#pragma unroll
    for (int o = 16; o; o >>= 1) {
        a += __shfl_xor_sync(0xffffffffu, a, o);
        b += __shfl_xor_sync(0xffffffffu, b, o);
    }
    int w = threadIdx.x >> 5;
    if ((threadIdx.x & 31) == 0) { s[w] = a; s[8 + w] = b; }
    __syncthreads();
    if (threadIdx.x < 32) {
        float ta = (threadIdx.x < 8) ? s[threadIdx.x] : 0.0f;
        float tb = (threadIdx.x < 8) ? s[8 + threadIdx.x] : 0.0f;
#pragma unroll
        for (int o = 4; o; o >>= 1) {
            ta += __shfl_xor_sync(0xffffffffu, ta, o);
            tb += __shfl_xor_sync(0xffffffffu, tb, o);
        }
        if (threadIdx.x == 0) { s[0] = ta; s[8] = tb; }
    }
    __syncthreads();
    a = s[0];
    b = s[8];
    __syncthreads();
}

// ---- fused block max/min of orderable keys ----
__device__ __forceinline__ void block_minmax_u(uint32_t& vmax, uint32_t& vmin, uint32_t* s) {
#pragma unroll
    for (int o = 16; o; o >>= 1) {
        vmax = max(vmax, __shfl_xor_sync(0xffffffffu, vmax, o));
        vmin = min(vmin, __shfl_xor_sync(0xffffffffu, vmin, o));
    }
    int w = threadIdx.x >> 5;
    if ((threadIdx.x & 31) == 0) { s[w] = vmax; s[8 + w] = vmin; }
    __syncthreads();
    if (threadIdx.x < 32) {
        uint32_t ta = (threadIdx.x < 8) ? s[threadIdx.x] : 0u;
        uint32_t tb = (threadIdx.x < 8) ? s[8 + threadIdx.x] : 0xFFFFFFFFu;
#pragma unroll
        for (int o = 4; o; o >>= 1) {
            ta = max(ta, __shfl_xor_sync(0xffffffffu, ta, o));
            tb = min(tb, __shfl_xor_sync(0xffffffffu, tb, o));
        }
        if (threadIdx.x == 0) { s[0] = ta; s[8] = tb; }
    }
    __syncthreads();
    vmax = s[0];
    vmin = s[8];
    __syncthreads();
}

__device__ __forceinline__ unsigned long long block_sum_u64(unsigned long long v,
                                                            unsigned long long* s) {
#pragma unroll
    for (int o = 16; o; o >>= 1) v += __shfl_xor_sync(0xffffffffu, v, o);
    int w = threadIdx.x >> 5;
    if ((threadIdx.x & 31) == 0) s[w] = v;
    __syncthreads();
    if (threadIdx.x < 32) {
        unsigned long long t = (threadIdx.x < 8) ? s[threadIdx.x] : 0ull;
#pragma unroll
        for (int o = 4; o; o >>= 1) t += __shfl_xor_sync(0xffffffffu, t, o);
        if (threadIdx.x == 0) s[0] = t;
    }
    __syncthreads();
    unsigned long long r = s[0];
    __syncthreads();
    return r;
}

// ---- block exclusive scan of a packed u64 (two independent u32 halves) ----
__device__ __forceinline__ unsigned long long block_exscan_u64(unsigned long long v,
                                                               unsigned long long* stot) {
    const uint32_t full = 0xffffffffu;
    int lane = threadIdx.x & 31, w = threadIdx.x >> 5;
    unsigned long long inc = v;
#pragma unroll
    for (int o = 1; o < 32; o <<= 1) {
        unsigned long long t = __shfl_up_sync(full, inc, o);
        if (lane >= o) inc += t;
    }
    if (lane == 31) stot[w] = inc;
    __syncthreads();
    if (threadIdx.x < 32) {
        unsigned long long t = (lane < 8) ? stot[lane] : 0ull;
        unsigned long long it = t;
#pragma unroll
        for (int o = 1; o < 8; o <<= 1) {
            unsigned long long x = __shfl_up_sync(full, it, o);
            if (lane >= o) it += x;
        }
        if (lane < 8) stot[lane] = it - t;  // exclusive warp offsets
    }
    __syncthreads();
    unsigned long long r = (inc - v) + stot[w];
    __syncthreads();   // protect stot reuse across calls
    return r;
}

__global__ __launch_bounds__(NT, 4)
void portfolio_kernel(const float* __restrict__ scores,
                      const float* __restrict__ short_ratio,
                      float* __restrict__ out) {
    const int row = blockIdx.x;
    const int tid = threadIdx.x;

    __shared__ uint32_t su[S];                 // keys, for rare tie-break only
    __shared__ uint32_t hA[1024];              // W histogram
    __shared__ uint32_t hB[1024];              // L histogram
    __shared__ unsigned long long stot[8];
    __shared__ unsigned long long w4[8][4];    // pass-1 per-warp partials
    __shared__ unsigned long long htot[4];     // pass-1 16-bin totals (16-bit lanes)
    __shared__ uint32_t shres[4];
    __shared__ float sredf[16];
    __shared__ uint32_t sredm[16];
    __shared__ unsigned long long sredu[8];

    // ---- load row into REGISTERS (and smem copy for tie-break), track max/min ----
    const float4* rowp = reinterpret_cast<const float4*>(scores + (size_t)row * S);
    uint32_t ur[8];
    uint32_t umax = 0u, umin = 0xFFFFFFFFu;
#pragma unroll
    for (int k = 0; k < 2; k++) {
        float4 v = rowp[tid + k * NT];
        int j = (tid + k * NT) * 4;
        uint32_t a = f2u(v.x), b = f2u(v.y), c = f2u(v.z), d = f2u(v.w);
        ur[k * 4 + 0] = a; ur[k * 4 + 1] = b; ur[k * 4 + 2] = c; ur[k * 4 + 3] = d;
        su[j + 0] = a; su[j + 1] = b; su[j + 2] = c; su[j + 3] = d;
        umax = max(umax, max(max(a, b), max(c, d)));
        umin = min(umin, min(min(a, b), min(c, d)));
    }
    // clear pass-2 histograms while loads land
#pragma unroll
    for (int k = 0; k < 4; k++) { hA[tid * 4 + k] = 0; hB[tid * 4 + k] = 0; }

    // ---- pass 1: top 4 bits, nibble-packed register histogram (NO atomics) ----
    unsigned long long cnt = 0ull;
#pragma unroll
    for (int k = 0; k < EPT; k++) cnt += 1ull << ((ur[k] >> 28) * 4);
    unsigned long long e0, e1, e2, e3;
    {
        // expand 16 nibbles -> 4 u64s of 4x16-bit lanes
        e0 = (cnt & 0xFull) | (((cnt >> 4) & 0xFull) << 16) |
             (((cnt >> 8) & 0xFull) << 32) | (((cnt >> 12) & 0xFull) << 48);
        e1 = ((cnt >> 16) & 0xFull) | (((cnt >> 20) & 0xFull) << 16) |
             (((cnt >> 24) & 0xFull) << 32) | (((cnt >> 28) & 0xFull) << 48);
        e2 = ((cnt >> 32) & 0xFull) | (((cnt >> 36) & 0xFull) << 16) |
             (((cnt >> 40) & 0xFull) << 32) | (((cnt >> 44) & 0xFull) << 48);
        e3 = ((cnt >> 48) & 0xFull) | (((cnt >> 52) & 0xFull) << 16) |
             (((cnt >> 56) & 0xFull) << 32) | (((cnt >> 60) & 0xFull) << 48);
#pragma unroll
        for (int o = 16; o; o >>= 1) {
            e0 += __shfl_xor_sync(0xffffffffu, e0, o);
            e1 += __shfl_xor_sync(0xffffffffu, e1, o);
            e2 += __shfl_xor_sync(0xffffffffu, e2, o);
            e3 += __shfl_xor_sync(0xffffffffu, e3, o);
        }
        int w = tid >> 5;
        if ((tid & 31) == 0) { w4[w][0] = e0; w4[w][1] = e1; w4[w][2] = e2; w4[w][3] = e3; }
    }
    __syncthreads();
    if (tid < 4) {
        unsigned long long t = 0ull;
#pragma unroll
        for (int w = 0; w < 8; w++) t += w4[w][tid];
        htot[tid] = t;
    }
    __syncthreads();

    block_minmax_u(umax, umin, sredm);
    const float maxF = u2f(umax);
    const float minF = u2f(umin);

    // every thread redundantly locates both ranks in the 16-bin histogram
    uint32_t rW = (uint32_t)(S - G + 1);   // 1793 ascending
    uint32_t rL = (uint32_t)G;             // 256  ascending
    uint32_t pW = 0, pL = 0;
    {
        unsigned long long h0 = htot[0], h1 = htot[1], h2 = htot[2], h3 = htot[3];
        uint32_t run = 0;
#pragma unroll
        for (int i = 0; i < 16; i++) {
            unsigned long long src = (i < 4) ? h0 : (i < 8) ? h1 : (i < 12) ? h2 : h3;
            uint32_t c = (uint32_t)((src >> (16 * (i & 3))) & 0xFFFFull);
            if (rW > run && rW <= run + c) { pW = (uint32_t)i; }
            if (rL > run && rL <= run + c) { pL = (uint32_t)i; }
            run += c;
        }
        // rank remainders
        run = 0;
#pragma unroll
        for (int i = 0; i < 16; i++) {
            unsigned long long src = (i < 4) ? h0 : (i < 8) ? h1 : (i < 12) ? h2 : h3;
            uint32_t c = (uint32_t)((src >> (16 * (i & 3))) & 0xFFFFull);
            if ((uint32_t)i == pW) rW -= run;
            if ((uint32_t)i == pL) rL -= run;
            if ((uint32_t)i < pW || (uint32_t)i < pL) {}  // keep structure simple
            run += c;
        }
    }
    // recompute remainders cleanly (above loop subtracted prefix once)
    __syncthreads();

    // ---- pass 2: bits 27..18 (1024 bins), sparse atomics ----
#pragma unroll
    for (int k = 0; k < EPT; k++) {
        uint32_t u = ur[k];
        uint32_t hi = u >> 28;
        if (hi == pW) atomicAdd(&hA[(u >> 18) & 0x3FFu], 1u);
        if (hi == pL) atomicAdd(&hB[(u >> 18) & 0x3FFu], 1u);
    }
    __syncthreads();
    {
        uint32_t ca[4], cb[4], sa = 0, sb = 0;
#pragma unroll
        for (int k = 0; k < 4; k++) {
            ca[k] = hA[tid * 4 + k]; hA[tid * 4 + k] = 0; sa += ca[k];
            cb[k] = hB[tid * 4 + k]; hB[tid * 4 + k] = 0; sb += cb[k];
        }
        unsigned long long e =
            block_exscan_u64((unsigned long long)sa | ((unsigned long long)sb << 32), stot);
        uint32_t ea = (uint32_t)e, eb = (uint32_t)(e >> 32);
        if (ea < rW && rW <= ea + sa) {
            uint32_t run = ea;
#pragma unroll
            for (int k = 0; k < 4; k++) {
                if (rW > run && rW <= run + ca[k]) { shres[0] = tid * 4 + k; shres[1] = rW - run; }
                run += ca[k];
            }
        }
        if (eb < rL && rL <= eb + sb) {
            uint32_t run = eb;
#pragma unroll
            for (int k = 0; k < 4; k++) {
                if (rL > run && rL <= run + cb[k]) { shres[2] = tid * 4 + k; shres[3] = rL - run; }
                run += cb[k];
            }
        }
        __syncthreads();
    }
    const uint32_t pfxW14 = (pW << 10) | shres[0]; rW = shres[1];
    const uint32_t pfxL14 = (pL << 10) | shres[2]; rL = shres[3];
    __syncthreads();

    // ---- pass 3: bits 17..8 (1024 bins) ----
#pragma unroll
    for (int k = 0; k < EPT; k++) {
        uint32_t u = ur[k];
        uint32_t hi = u >> 18;
        if (hi == pfxW14) atomicAdd(&hA[(u >> 8) & 0x3FFu], 1u);
        if (hi == pfxL14) atomicAdd(&hB[(u >> 8) & 0x3FFu], 1u);
    }
    __syncthreads();
    {
        uint32_t ca[4], cb[4], sa = 0, sb = 0;
#pragma unroll
        for (int k = 0; k < 4; k++) {
            ca[k] = hA[tid * 4 + k]; hA[tid * 4 + k] = 0; sa += ca[k];
            cb[k] = hB[tid * 4 + k]; hB[tid * 4 + k] = 0; sb += cb[k];
        }
        unsigned long long e =
            block_exscan_u64((unsigned long long)sa | ((unsigned long long)sb << 32), stot);
        uint32_t ea = (uint32_t)e, eb = (uint32_t)(e >> 32);
        if (ea < rW && rW <= ea + sa) {
            uint32_t run = ea;
#pragma unroll
            for (int k = 0; k < 4; k++) {
                if (rW > run && rW <= run + ca[k]) { shres[0] = tid * 4 + k; shres[1] = rW - run; }
                run += ca[k];
            }
        }
        if (eb < rL && rL <= eb + sb) {
            uint32_t run = eb;
#pragma unroll
            for (int k = 0; k < 4; k++) {
                if (rL > run && rL <= run + cb[k]) { shres[2] = tid * 4 + k; shres[3] = rL - run; }
                run += cb[k];
            }
        }
        __syncthreads();
    }
    const uint32_t pfxW24 = (pfxW14 << 10) | shres[0]; rW = shres[1];
    const uint32_t pfxL24 = (pfxL14 << 10) | shres[2]; rL = shres[3];
    __syncthreads();

    // ---- pass 4: bits 7..0 (256 bins, 1 per thread) ----
#pragma unroll
    for (int k = 0; k < EPT; k++) {
        uint32_t u = ur[k];
        uint32_t hi = u >> 8;
        if (hi == pfxW24) atomicAdd(&hA[u & 0xFFu], 1u);
        if (hi == pfxL24) atomicAdd(&hB[u & 0xFFu], 1u);
    }
    __syncthreads();
    {
        uint32_t sa = hA[tid]; hA[tid] = 0;
        uint32_t sb = hB[tid]; hB[tid] = 0;
        unsigned long long e =
            block_exscan_u64((unsigned long long)sa | ((unsigned long long)sb << 32), stot);
        uint32_t ea = (uint32_t)e, eb = (uint32_t)(e >> 32);
        if (ea < rW && rW <= ea + sa) shres[0] = (uint32_t)tid;
        if (eb < rL && rL <= eb + sb) shres[2] = (uint32_t)tid;
        __syncthreads();
    }
    const uint32_t uw = (pfxW24 << 8) | shres[0];
    const uint32_t ul = (pfxL24 << 8) | shres[2];
    __syncthreads();

    const float sw_val = u2f(uw);
    const float sl_val = u2f(ul);

    // ---- counts + exp-sums for strict winners/losers (registers) ----
    uint32_t cWgt = 0, cWeq = 0, cLlt = 0, cLeq = 0;
    float sW = 0.0f, sL = 0.0f;
#pragma unroll
    for (int k = 0; k < EPT; k++) {
        uint32_t u = ur[k];
        float s = u2f(u);
        if (u > uw) { cWgt++; sW += __expf(s - maxF); }
        else if (u == uw) { cWeq++; }
        if (u < ul) { cLlt++; sL += __expf(minF - s); }
        else if (u == ul) { cLeq++; }
    }
    unsigned long long packed =
        (unsigned long long)cWgt | ((unsigned long long)cWeq << 16) |
        ((unsigned long long)cLlt << 32) | ((unsigned long long)cLeq << 48);
    packed = block_sum_u64(packed, sredu);
    const int nWgt = (int)(packed & 0xFFFFu);
    const int nWeq = (int)((packed >> 16) & 0xFFFFu);
    const int nLlt = (int)((packed >> 32) & 0xFFFFu);
    const int nLeq = (int)((packed >> 48) & 0xFFFFu);

    const int eW = G - nWgt;   // equals-at-threshold to include (>=1)
    const int eL = G - nLlt;

    block_sum2_f(sW, sL, sredf);

    const float expWeq = __expf(sw_val - maxF);
    const float expLeq = __expf(minF - sl_val);
    const float invW = 1.0f / (sW + (float)eW * expWeq);
    const float invL = 1.0f / (sL + (float)eL * expLeq);
    const float wEq = expWeq * invW;
    const float lEq = expLeq * invL;

    // ---- write both weight planes, coalesced float4, from registers ----
    float4* outL = reinterpret_cast<float4*>(out + (size_t)row * S);
    float4* outSh = reinterpret_cast<float4*>(out + (size_t)BATCH * S + (size_t)row * S);
#pragma unroll
    for (int k = 0; k < 2; k++) {
        int q = tid + k * NT;      // float4 slot
        int base = q * 4;
        float lw[4], sw4[4];
#pragma unroll
        for (int c = 0; c < 4; c++) {
            int j = base + c;
            uint32_t u = ur[k * 4 + c];
            float s = u2f(u);
            float lval = 0.0f, sval = 0.0f;
            if (u > uw) {
                lval = __expf(s - maxF) * invW;
            } else if (u == uw) {
                if (nWeq == eW) {
                    lval = wEq;
                } else {  // rare boundary tie: rank among equals by index
                    int before = 0;
                    for (int m = 0; m < j; m++) before += (su[m] == uw);
                    if (before < eW) lval = wEq;
                }
            }
            if (u < ul) {
                sval = __expf(minF - s) * invL;
            } else if (u == ul) {
                if (nLeq == eL) {
                    sval = lEq;
                } else {
                    int before = 0;
                    for (int m = 0; m < j; m++) before += (su[m] == ul);
                    if (before < eL) sval = lEq;
                }
            }
            lw[c] = lval;
            sw4[c] = sval;
        }
        outL[q]  = make_float4(lw[0], lw[1], lw[2], lw[3]);
        outSh[q] = make_float4(sw4[0], sw4[1], sw4[2], sw4[3]);
    }

    // ---- short_ratio passthrough (clipped) ----
    if (tid == 0) {
        float r = short_ratio[row];
        r = fminf(fmaxf(r, 0.0f), 1.0f);
        out[(size_t)2 * BATCH * S + row] = r;
    }
}

extern "C" void kernel_launch(void* const* d_in, const int* in_sizes, int n_in,
                              void* d_out, int out_size) {
    const float* scores = (const float*)d_in[0];
    const float* ratio  = (const float*)d_in[1];
    // defensive: identify by size (scores is BATCH*S, ratio is BATCH)
    if (n_in >= 2 && in_sizes[0] == BATCH && in_sizes[1] == BATCH * S) {
        const float* t = scores; scores = ratio; ratio = t;
    }
    portfolio_kernel<<<BATCH, NT>>>(scores, ratio, (float*)d_out);
}

// round 4
// speedup vs baseline: 1.4839x; 1.3096x over previous
#include <cuda_runtime.h>
#include <cstdint>
#include <math_constants.h>

#define BATCH   16384
#define S       2048
#define G       256
#define NT      256
#define EPT     (S / NT)   // 8
#define LISTCAP 32

// ---- order-preserving float<->uint transforms ----
__device__ __forceinline__ uint32_t f2u(float f) {
    uint32_t b = __float_as_uint(f);
    return b ^ ((b & 0x80000000u) ? 0xFFFFFFFFu : 0x80000000u);
}
__device__ __forceinline__ float u2f(uint32_t u) {
    uint32_t b = (u & 0x80000000u) ? (u ^ 0x80000000u) : ~u;
    return __uint_as_float(b);
}

// ---- block exclusive scan of a packed u64 (two independent u32 halves) ----
__device__ __forceinline__ unsigned long long block_exscan_u64(unsigned long long v,
                                                               unsigned long long* stot) {
    const uint32_t full = 0xffffffffu;
    int lane = threadIdx.x & 31, w = threadIdx.x >> 5;
    unsigned long long inc = v;
#pragma unroll
    for (int o = 1; o < 32; o <<= 1) {
        unsigned long long t = __shfl_up_sync(full, inc, o);
        if (lane >= o) inc += t;
    }
    if (lane == 31) stot[w] = inc;
    __syncthreads();
    if (threadIdx.x < 32) {
        unsigned long long t = (lane < 8) ? stot[lane] : 0ull;
        unsigned long long it = t;
#pragma unroll
        for (int o = 1; o < 8; o <<= 1) {
            unsigned long long x = __shfl_up_sync(full, it, o);
            if (lane >= o) it += x;
        }
        if (lane < 8) stot[lane] = it - t;  // exclusive warp offsets
    }
    __syncthreads();
    unsigned long long r = (inc - v) + stot[w];
    __syncthreads();   // protect stot reuse across calls
    return r;
}

__global__ __launch_bounds__(NT, 5)
void portfolio_kernel(const float* __restrict__ scores,
                      const float* __restrict__ short_ratio,
                      float* __restrict__ out) {
    const int row = blockIdx.x;
    const int tid = threadIdx.x;
    const int lane = tid & 31;
    const int wid = tid >> 5;

    __shared__ uint32_t su[S];                 // keys, for rare tie-break only
    __shared__ uint32_t hA[1024];              // W histogram
    __shared__ uint32_t hB[1024];              // L histogram
    __shared__ unsigned long long stot[8];
    __shared__ unsigned long long w4[8][4];    // pass-1 per-warp 16 bins (16-bit lanes)
    __shared__ uint32_t wmax[8], wmin[8];
    __shared__ uint32_t pub[8];
    __shared__ uint32_t cnt2[2];
    __shared__ uint32_t listW[LISTCAP], listL[LISTCAP];
    __shared__ float sredf[16];
    __shared__ unsigned long long sredu[8];

    // ---- load row into registers (+smem copy for tie-break), local max/min ----
    const float4* rowp = reinterpret_cast<const float4*>(scores + (size_t)row * S);
    uint32_t ur[8];
    uint32_t umax = 0u, umin = 0xFFFFFFFFu;
#pragma unroll
    for (int k = 0; k < 2; k++) {
        float4 v = rowp[tid + k * NT];
        int j = (tid + k * NT) * 4;
        uint32_t a = f2u(v.x), b = f2u(v.y), c = f2u(v.z), d = f2u(v.w);
        ur[k * 4 + 0] = a; ur[k * 4 + 1] = b; ur[k * 4 + 2] = c; ur[k * 4 + 3] = d;
        su[j + 0] = a; su[j + 1] = b; su[j + 2] = c; su[j + 3] = d;
        umax = max(umax, max(max(a, b), max(c, d)));
        umin = min(umin, min(min(a, b), min(c, d)));
    }
    // clear pass-2 histograms + counters while loads land
#pragma unroll
    for (int k = 0; k < 4; k++) { hA[tid * 4 + k] = 0; hB[tid * 4 + k] = 0; }
    if (tid < 2) cnt2[tid] = 0;

    // ---- pass 1: top 4 bits, register nibble histogram, byte-wise butterfly ----
    unsigned long long cnt = 0ull;
#pragma unroll
    for (int k = 0; k < EPT; k++) cnt += 1ull << ((ur[k] >> 28) * 4);
    unsigned long long be = cnt & 0x0F0F0F0F0F0F0F0Full;          // digits 0,2,..,14
    unsigned long long bo = (cnt >> 4) & 0x0F0F0F0F0F0F0F0Full;   // digits 1,3,..,15
#pragma unroll
    for (int o = 1; o <= 8; o <<= 1) {   // byte lanes, max 8*16=128 < 256
        be += __shfl_xor_sync(0xffffffffu, be, o);
        bo += __shfl_xor_sync(0xffffffffu, bo, o);
        umax = max(umax, __shfl_xor_sync(0xffffffffu, umax, o));
        umin = min(umin, __shfl_xor_sync(0xffffffffu, umin, o));
    }
    {
        const unsigned long long m16 = 0x00FF00FF00FF00FFull;
        unsigned long long q0 = be & m16;           // digits 0,4,8,12
        unsigned long long q1 = (be >> 8) & m16;    // digits 2,6,10,14
        unsigned long long q2 = bo & m16;           // digits 1,5,9,13
        unsigned long long q3 = (bo >> 8) & m16;    // digits 3,7,11,15
        q0 += __shfl_xor_sync(0xffffffffu, q0, 16);
        q1 += __shfl_xor_sync(0xffffffffu, q1, 16);
        q2 += __shfl_xor_sync(0xffffffffu, q2, 16);
        q3 += __shfl_xor_sync(0xffffffffu, q3, 16);
        umax = max(umax, __shfl_xor_sync(0xffffffffu, umax, 16));
        umin = min(umin, __shfl_xor_sync(0xffffffffu, umin, 16));
        if (lane == 0) {
            w4[wid][0] = q0; w4[wid][1] = q1; w4[wid][2] = q2; w4[wid][3] = q3;
            wmax[wid] = umax; wmin[wid] = umin;
        }
    }
    __syncthreads();

    // thread 0 alone decodes the 16-bin histogram and locates both ranks
    if (tid == 0) {
        unsigned long long t0 = 0, t1 = 0, t2 = 0, t3 = 0;
        uint32_t gmax = 0u, gmin = 0xFFFFFFFFu;
#pragma unroll
        for (int w = 0; w < 8; w++) {
            t0 += w4[w][0]; t1 += w4[w][1]; t2 += w4[w][2]; t3 += w4[w][3];
            gmax = max(gmax, wmax[w]); gmin = min(gmin, wmin[w]);
        }
        uint32_t rW = (uint32_t)(S - G + 1), rL = (uint32_t)G;
        uint32_t run = 0, pW = 0, pL = 0, rWr = 0, rLr = 0;
#pragma unroll
        for (int d = 0; d < 16; d++) {
            int idx = ((d & 1) << 1) | ((d >> 1) & 1);
            unsigned long long src = (idx == 0) ? t0 : (idx == 1) ? t1 : (idx == 2) ? t2 : t3;
            uint32_t c = (uint32_t)((src >> (16 * (d >> 2))) & 0xFFFFull);
            if (rW > run && rW <= run + c) { pW = (uint32_t)d; rWr = rW - run; }
            if (rL > run && rL <= run + c) { pL = (uint32_t)d; rLr = rL - run; }
            run += c;
        }
        pub[0] = pW; pub[1] = rWr; pub[2] = pL; pub[3] = rLr;
        pub[4] = gmax; pub[5] = gmin;
    }
    __syncthreads();
    const uint32_t pW = pub[0]; uint32_t rW = pub[1];
    const uint32_t pL = pub[2]; uint32_t rL = pub[3];
    const float maxF = u2f(pub[4]);
    const float minF = u2f(pub[5]);

    // ---- pass 2: bits 27..18 (1024 bins), sparse atomics ----
#pragma unroll
    for (int k = 0; k < EPT; k++) {
        uint32_t u = ur[k];
        uint32_t hi = u >> 28;
        if (hi == pW) atomicAdd(&hA[(u >> 18) & 0x3FFu], 1u);
        if (hi == pL) atomicAdd(&hB[(u >> 18) & 0x3FFu], 1u);
    }
    __syncthreads();
    {
        uint32_t ca[4], cb[4], sa = 0, sb = 0;
#pragma unroll
        for (int k = 0; k < 4; k++) {
            ca[k] = hA[tid * 4 + k]; hA[tid * 4 + k] = 0; sa += ca[k];
            cb[k] = hB[tid * 4 + k]; hB[tid * 4 + k] = 0; sb += cb[k];
        }
        unsigned long long e =
            block_exscan_u64((unsigned long long)sa | ((unsigned long long)sb << 32), stot);
        uint32_t ea = (uint32_t)e, eb = (uint32_t)(e >> 32);
        if (ea < rW && rW <= ea + sa) {
            uint32_t run = ea;
#pragma unroll
            for (int k = 0; k < 4; k++) {
                if (rW > run && rW <= run + ca[k]) { pub[0] = tid * 4 + k; pub[1] = rW - run; }
                run += ca[k];
            }
        }
        if (eb < rL && rL <= eb + sb) {
            uint32_t run = eb;
#pragma unroll
            for (int k = 0; k < 4; k++) {
                if (rL > run && rL <= run + cb[k]) { pub[2] = tid * 4 + k; pub[3] = rL - run; }
                run += cb[k];
            }
        }
        __syncthreads();
    }
    const uint32_t pfxW14 = (pW << 10) | pub[0]; rW = pub[1];
    const uint32_t pfxL14 = (pL << 10) | pub[2]; rL = pub[3];
    __syncthreads();

    // ---- capture crossing-bin members (expected O(1) each) ----
#pragma unroll
    for (int k = 0; k < EPT; k++) {
        uint32_t u = ur[k];
        if ((u >> 18) == pfxW14) {
            uint32_t i = atomicAdd(&cnt2[0], 1u);
            if (i < LISTCAP) listW[i] = u;
        }
        if ((u >> 18) == pfxL14) {
            uint32_t i = atomicAdd(&cnt2[1], 1u);
            if (i < LISTCAP) listL[i] = u;
        }
    }
    __syncthreads();
    const uint32_t cW = cnt2[0], cL = cnt2[1];

    if (cW <= LISTCAP && cL <= LISTCAP) {
        // ---- FAST: warp 0 sorts listW, warp 1 sorts listL (bitonic, ascending) ----
        if (wid < 2) {
            const uint32_t n = (wid == 0) ? cW : cL;
            uint32_t v = ((uint32_t)lane < n) ? (wid == 0 ? listW[lane] : listL[lane])
                                              : 0xFFFFFFFFu;
#pragma unroll
            for (int k = 2; k <= 32; k <<= 1) {
#pragma unroll
                for (int j = k >> 1; j > 0; j >>= 1) {
                    uint32_t o = __shfl_xor_sync(0xffffffffu, v, j);
                    bool up = ((lane & k) == 0);
                    bool lower = ((lane & j) == 0);
                    uint32_t mn = min(v, o), mx = max(v, o);
                    v = ((lower == up)) ? mn : mx;
                }
            }
            uint32_t rank = (wid == 0) ? rW : rL;   // 1-based, <= n <= 32
            uint32_t sel = __shfl_sync(0xffffffffu, v, (int)(rank - 1));
            if (lane == 0) pub[wid] = sel;
        }
        __syncthreads();
    } else {
        // ---- SLOW fallback: pass 3 (bits 17..8) + pass 4 (bits 7..0) ----
#pragma unroll
        for (int k = 0; k < EPT; k++) {
            uint32_t u = ur[k];
            if ((u >> 18) == pfxW14) atomicAdd(&hA[(u >> 8) & 0x3FFu], 1u);
            if ((u >> 18) == pfxL14) atomicAdd(&hB[(u >> 8) & 0x3FFu], 1u);
        }
        __syncthreads();
        {
            uint32_t ca[4], cb[4], sa = 0, sb = 0;
#pragma unroll
            for (int k = 0; k < 4; k++) {
                ca[k] = hA[tid * 4 + k]; hA[tid * 4 + k] = 0; sa += ca[k];
                cb[k] = hB[tid * 4 + k]; hB[tid * 4 + k] = 0; sb += cb[k];
            }
            unsigned long long e =
                block_exscan_u64((unsigned long long)sa | ((unsigned long long)sb << 32), stot);
            uint32_t ea = (uint32_t)e, eb = (uint32_t)(e >> 32);
            if (ea < rW && rW <= ea + sa) {
                uint32_t run = ea;
#pragma unroll
                for (int k = 0; k < 4; k++) {
                    if (rW > run && rW <= run + ca[k]) { pub[0] = tid * 4 + k; pub[1] = rW - run; }
                    run += ca[k];
                }
            }
            if (eb < rL && rL <= eb + sb) {
                uint32_t run = eb;
#pragma unroll
                for (int k = 0; k < 4; k++) {
                    if (rL > run && rL <= run + cb[k]) { pub[2] = tid * 4 + k; pub[3] = rL - run; }
                    run += cb[k];
                }
            }
            __syncthreads();
        }
        const uint32_t pfxW24 = (pfxW14 << 10) | pub[0]; rW = pub[1];
        const uint32_t pfxL24 = (pfxL14 << 10) | pub[2]; rL = pub[3];
        __syncthreads();
#pragma unroll
        for (int k = 0; k < EPT; k++) {
            uint32_t u = ur[k];
            if ((u >> 8) == pfxW24) atomicAdd(&hA[u & 0xFFu], 1u);
            if ((u >> 8) == pfxL24) atomicAdd(&hB[u & 0xFFu], 1u);
        }
        __syncthreads();
        {
            uint32_t sa = hA[tid]; hA[tid] = 0;
            uint32_t sb = hB[tid]; hB[tid] = 0;
            unsigned long long e =
                block_exscan_u64((unsigned long long)sa | ((unsigned long long)sb << 32), stot);
            uint32_t ea = (uint32_t)e, eb = (uint32_t)(e >> 32);
            if (ea < rW && rW <= ea + sa) pub[0] = (pfxW24 << 8) | (uint32_t)tid;
            if (eb < rL && rL <= eb + sb) pub[1] = (pfxL24 << 8) | (uint32_t)tid;
            __syncthreads();
        }
    }
    const uint32_t uw = pub[0];
    const uint32_t ul = pub[1];
    __syncthreads();

    const float sw_val = u2f(uw);
    const float sl_val = u2f(ul);

    // ---- counts + exp-sums for strict winners/losers (registers) ----
    uint32_t cWgt = 0, cWeq = 0, cLlt = 0, cLeq = 0;
    float sW = 0.0f, sL = 0.0f;
#pragma unroll
    for (int k = 0; k < EPT; k++) {
        uint32_t u = ur[k];
        float s = u2f(u);
        if (u > uw) { cWgt++; sW += __expf(s - maxF); }
        else if (u == uw) { cWeq++; }
        if (u < ul) { cLlt++; sL += __expf(minF - s); }
        else if (u == ul) { cLeq++; }
    }
    unsigned long long packed =
        (unsigned long long)cWgt | ((unsigned long long)cWeq << 16) |
        ((unsigned long long)cLlt << 32) | ((unsigned long long)cLeq << 48);
    // fused block reduction: packed + sW + sL
#pragma unroll
    for (int o = 16; o; o >>= 1) {
        packed += __shfl_xor_sync(0xffffffffu, packed, o);
        sW += __shfl_xor_sync(0xffffffffu, sW, o);
        sL += __shfl_xor_sync(0xffffffffu, sL, o);
    }
    if (lane == 0) { sredu[wid] = packed; sredf[wid] = sW; sredf[8 + wid] = sL; }
    __syncthreads();
    if (tid < 32) {
        unsigned long long c = (lane < 8) ? sredu[lane] : 0ull;
        float a = (lane < 8) ? sredf[lane] : 0.0f;
        float b = (lane < 8) ? sredf[8 + lane] : 0.0f;
#pragma unroll
        for (int o = 4; o; o >>= 1) {
            c += __shfl_xor_sync(0xffffffffu, c, o);
            a += __shfl_xor_sync(0xffffffffu, a, o);
            b += __shfl_xor_sync(0xffffffffu, b, o);
        }
        if (lane == 0) { sredu[0] = c; sredf[0] = a; sredf[8] = b; }
    }
    __syncthreads();
    packed = sredu[0];
    sW = sredf[0];
    sL = sredf[8];

    const int nWgt = (int)(packed & 0xFFFFu);
    const int nWeq = (int)((packed >> 16) & 0xFFFFu);
    const int nLlt = (int)((packed >> 32) & 0xFFFFu);
    const int nLeq = (int)((packed >> 48) & 0xFFFFu);
    const int eW = G - nWgt;   // equals-at-threshold to include (>=1)
    const int eL = G - nLlt;

    const float expWeq = __expf(sw_val - maxF);
    const float expLeq = __expf(minF - sl_val);
    const float invW = 1.0f / (sW + (float)eW * expWeq);
    const float invL = 1.0f / (sL + (float)eL * expLeq);
    const float wEq = expWeq * invW;
    const float lEq = expLeq * invL;

    // ---- write both weight planes, coalesced float4, from registers ----
    float4* outL = reinterpret_cast<float4*>(out + (size_t)row * S);
    float4* outSh = reinterpret_cast<float4*>(out + (size_t)BATCH * S + (size_t)row * S);
#pragma unroll
    for (int k = 0; k < 2; k++) {
        int q = tid + k * NT;      // float4 slot
        int base = q * 4;
        float lw[4], sw4[4];
#pragma unroll
        for (int c = 0; c < 4; c++) {
            int j = base + c;
            uint32_t u = ur[k * 4 + c];
            float s = u2f(u);
            float lval = 0.0f, sval = 0.0f;
            if (u > uw) {
                lval = __expf(s - maxF) * invW;
            } else if (u == uw) {
                if (nWeq == eW) {
                    lval = wEq;
                } else {  // rare boundary tie: rank among equals by index
                    int before = 0;
                    for (int m = 0; m < j; m++) before += (su[m] == uw);
                    if (before < eW) lval = wEq;
                }
            }
            if (u < ul) {
                sval = __expf(minF - s) * invL;
            } else if (u == ul) {
                if (nLeq == eL) {
                    sval = lEq;
                } else {
                    int before = 0;
                    for (int m = 0; m < j; m++) before += (su[m] == ul);
                    if (before < eL) sval = lEq;
                }
            }
            lw[c] = lval;
            sw4[c] = sval;
        }
        outL[q]  = make_float4(lw[0], lw[1], lw[2], lw[3]);
        outSh[q] = make_float4(sw4[0], sw4[1], sw4[2], sw4[3]);
    }

    // ---- short_ratio passthrough (clipped) ----
    if (tid == 0) {
        float r = short_ratio[row];
        r = fminf(fmaxf(r, 0.0f), 1.0f);
        out[(size_t)2 * BATCH * S + row] = r;
    }
}

extern "C" void kernel_launch(void* const* d_in, const int* in_sizes, int n_in,
                              void* d_out, int out_size) {
    const float* scores = (const float*)d_in[0];
    const float* ratio  = (const float*)d_in[1];
    // defensive: identify by size (scores is BATCH*S, ratio is BATCH)
    if (n_in >= 2 && in_sizes[0] == BATCH && in_sizes[1] == BATCH * S) {
        const float* t = scores; scores = ratio; ratio = t;
    }
    portfolio_kernel<<<BATCH, NT>>>(scores, ratio, (float*)d_out);
}

// round 5
// speedup vs baseline: 1.8083x; 1.2187x over previous
#include <cuda_runtime.h>
#include <cstdint>
#include <math_constants.h>

#define BATCH   16384
#define S       2048
#define G       256
#define NT      256
#define EPT     (S / NT)   // 8
#define LISTCAP 32

// ---- order-preserving float<->uint transforms ----
__device__ __forceinline__ uint32_t f2u(float f) {
    uint32_t b = __float_as_uint(f);
    return b ^ ((b & 0x80000000u) ? 0xFFFFFFFFu : 0x80000000u);
}
__device__ __forceinline__ float u2f(uint32_t u) {
    uint32_t b = (u & 0x80000000u) ? (u ^ 0x80000000u) : ~u;
    return __uint_as_float(b);
}

// ---- block exclusive scan of a packed u64 (independent 16/32-bit lanes, no carry) ----
__device__ __forceinline__ unsigned long long block_exscan_u64(unsigned long long v,
                                                               unsigned long long* stot) {
    const uint32_t full = 0xffffffffu;
    int lane = threadIdx.x & 31, w = threadIdx.x >> 5;
    unsigned long long inc = v;
#pragma unroll
    for (int o = 1; o < 32; o <<= 1) {
        unsigned long long t = __shfl_up_sync(full, inc, o);
        if (lane >= o) inc += t;
    }
    if (lane == 31) stot[w] = inc;
    __syncthreads();
    if (threadIdx.x < 32) {
        unsigned long long t = (lane < 8) ? stot[lane] : 0ull;
        unsigned long long it = t;
#pragma unroll
        for (int o = 1; o < 8; o <<= 1) {
            unsigned long long x = __shfl_up_sync(full, it, o);
            if (lane >= o) it += x;
        }
        if (lane < 8) stot[lane] = it - t;  // exclusive warp offsets
    }
    __syncthreads();
    unsigned long long r = (inc - v) + stot[w];
    __syncthreads();   // protect stot reuse across calls
    return r;
}

__global__ __launch_bounds__(NT, 6)
void portfolio_kernel(const float* __restrict__ scores,
                      const float* __restrict__ short_ratio,
                      float* __restrict__ out) {
    const int row = blockIdx.x;
    const int tid = threadIdx.x;
    const int lane = tid & 31;
    const int wid = tid >> 5;

    __shared__ __align__(16) uint32_t hA[1024];   // W histogram
    __shared__ __align__(16) uint32_t hB[1024];   // L histogram
    __shared__ unsigned long long stot[8];
    __shared__ unsigned long long w4[8][4];       // pass-1 per-warp 16 bins (16-bit lanes)
    __shared__ uint32_t wmax[8], wmin[8];
    __shared__ uint32_t pub[8];
    __shared__ uint32_t cnt2[2];
    __shared__ uint32_t listW[LISTCAP], listL[LISTCAP];
    __shared__ float sredf[16];
    __shared__ unsigned long long sredu[8];

    // ---- load row into registers, local max/min ----
    const float4* rowp = reinterpret_cast<const float4*>(scores + (size_t)row * S);
    uint32_t ur[8];
    uint32_t umax = 0u, umin = 0xFFFFFFFFu;
#pragma unroll
    for (int k = 0; k < 2; k++) {
        float4 v = rowp[tid + k * NT];
        uint32_t a = f2u(v.x), b = f2u(v.y), c = f2u(v.z), d = f2u(v.w);
        ur[k * 4 + 0] = a; ur[k * 4 + 1] = b; ur[k * 4 + 2] = c; ur[k * 4 + 3] = d;
        umax = max(umax, max(max(a, b), max(c, d)));
        umin = min(umin, min(min(a, b), min(c, d)));
    }
    // vector-clear pass-2 histograms + counters
    reinterpret_cast<uint4*>(hA)[tid] = make_uint4(0, 0, 0, 0);
    reinterpret_cast<uint4*>(hB)[tid] = make_uint4(0, 0, 0, 0);
    if (tid < 2) cnt2[tid] = 0;

    // warp min/max via REDUX
    umax = __reduce_max_sync(0xffffffffu, umax);
    umin = __reduce_min_sync(0xffffffffu, umin);
    if (lane == 0) { wmax[wid] = umax; wmin[wid] = umin; }

    // ---- pass 1: top 4 bits, register nibble histogram, byte-wise butterfly ----
    unsigned long long cnt = 0ull;
#pragma unroll
    for (int k = 0; k < EPT; k++) cnt += 1ull << ((ur[k] >> 28) * 4);
    unsigned long long be = cnt & 0x0F0F0F0F0F0F0F0Full;          // digits 0,2,..,14
    unsigned long long bo = (cnt >> 4) & 0x0F0F0F0F0F0F0F0Full;   // digits 1,3,..,15
#pragma unroll
    for (int o = 1; o <= 8; o <<= 1) {   // byte lanes, max 128 < 256
        be += __shfl_xor_sync(0xffffffffu, be, o);
        bo += __shfl_xor_sync(0xffffffffu, bo, o);
    }
    {
        const unsigned long long m16 = 0x00FF00FF00FF00FFull;
        unsigned long long q0 = be & m16;           // digits 0,4,8,12
        unsigned long long q1 = (be >> 8) & m16;    // digits 2,6,10,14
        unsigned long long q2 = bo & m16;           // digits 1,5,9,13
        unsigned long long q3 = (bo >> 8) & m16;    // digits 3,7,11,15
        q0 += __shfl_xor_sync(0xffffffffu, q0, 16);
        q1 += __shfl_xor_sync(0xffffffffu, q1, 16);
        q2 += __shfl_xor_sync(0xffffffffu, q2, 16);
        q3 += __shfl_xor_sync(0xffffffffu, q3, 16);
        if (lane == 0) {
            w4[wid][0] = q0; w4[wid][1] = q1; w4[wid][2] = q2; w4[wid][3] = q3;
        }
    }
    __syncthreads();

    // thread 0 decodes the 16-bin histogram and locates both ranks
    if (tid == 0) {
        unsigned long long t0 = 0, t1 = 0, t2 = 0, t3 = 0;
        uint32_t gmax = 0u, gmin = 0xFFFFFFFFu;
#pragma unroll
        for (int w = 0; w < 8; w++) {
            t0 += w4[w][0]; t1 += w4[w][1]; t2 += w4[w][2]; t3 += w4[w][3];
            gmax = max(gmax, wmax[w]); gmin = min(gmin, wmin[w]);
        }
        uint32_t rWt = (uint32_t)(S - G + 1), rLt = (uint32_t)G;
        uint32_t run = 0, pWv = 0, pLv = 0, rWr = 0, rLr = 0;
#pragma unroll
        for (int d = 0; d < 16; d++) {
            int idx = ((d & 1) << 1) | ((d >> 1) & 1);
            unsigned long long src = (idx == 0) ? t0 : (idx == 1) ? t1 : (idx == 2) ? t2 : t3;
            uint32_t c = (uint32_t)((src >> (16 * (d >> 2))) & 0xFFFFull);
            if (rWt > run && rWt <= run + c) { pWv = (uint32_t)d; rWr = rWt - run; }
            if (rLt > run && rLt <= run + c) { pLv = (uint32_t)d; rLr = rLt - run; }
            run += c;
        }
        pub[0] = pWv; pub[1] = rWr; pub[2] = pLv; pub[3] = rLr;
        pub[4] = gmax; pub[5] = gmin;
    }
    __syncthreads();
    const uint32_t pW = pub[0]; uint32_t rW = pub[1];
    const uint32_t pL = pub[2]; uint32_t rL = pub[3];
    const float maxF = u2f(pub[4]);
    const float minF = u2f(pub[5]);

    // ---- pass 2: bits 27..18 (1024 bins), sparse atomics ----
#pragma unroll
    for (int k = 0; k < EPT; k++) {
        uint32_t u = ur[k];
        uint32_t hi = u >> 28;
        if (hi == pW) atomicAdd(&hA[(u >> 18) & 0x3FFu], 1u);
        if (hi == pL) atomicAdd(&hB[(u >> 18) & 0x3FFu], 1u);
    }
    __syncthreads();
    {
        uint4 va = reinterpret_cast<uint4*>(hA)[tid];
        uint4 vb = reinterpret_cast<uint4*>(hB)[tid];
        reinterpret_cast<uint4*>(hA)[tid] = make_uint4(0, 0, 0, 0);
        reinterpret_cast<uint4*>(hB)[tid] = make_uint4(0, 0, 0, 0);
        uint32_t ca[4] = {va.x, va.y, va.z, va.w};
        uint32_t cb[4] = {vb.x, vb.y, vb.z, vb.w};
        uint32_t sa = ca[0] + ca[1] + ca[2] + ca[3];
        uint32_t sb = cb[0] + cb[1] + cb[2] + cb[3];
        unsigned long long e =
            block_exscan_u64((unsigned long long)sa | ((unsigned long long)sb << 32), stot);
        uint32_t ea = (uint32_t)e, eb = (uint32_t)(e >> 32);
        if (ea < rW && rW <= ea + sa) {
            uint32_t run = ea;
#pragma unroll
            for (int k = 0; k < 4; k++) {
                if (rW > run && rW <= run + ca[k]) { pub[0] = tid * 4 + k; pub[1] = rW - run; }
                run += ca[k];
            }
        }
        if (eb < rL && rL <= eb + sb) {
            uint32_t run = eb;
#pragma unroll
            for (int k = 0; k < 4; k++) {
                if (rL > run && rL <= run + cb[k]) { pub[2] = tid * 4 + k; pub[3] = rL - run; }
                run += cb[k];
            }
        }
        __syncthreads();
    }
    const uint32_t pfxW14 = (pW << 10) | pub[0]; rW = pub[1];
    const uint32_t pfxL14 = (pL << 10) | pub[2]; rL = pub[3];
    __syncthreads();

    // ---- capture crossing-bin members (expected O(10) each) ----
#pragma unroll
    for (int k = 0; k < EPT; k++) {
        uint32_t u = ur[k];
        if ((u >> 18) == pfxW14) {
            uint32_t i = atomicAdd(&cnt2[0], 1u);
            if (i < LISTCAP) listW[i] = u;
        }
        if ((u >> 18) == pfxL14) {
            uint32_t i = atomicAdd(&cnt2[1], 1u);
            if (i < LISTCAP) listL[i] = u;
        }
    }
    __syncthreads();
    const uint32_t cW = cnt2[0], cL = cnt2[1];

    if (cW <= LISTCAP && cL <= LISTCAP) {
        // ---- FAST: warp 0 sorts listW, warp 1 sorts listL (bitonic, ascending) ----
        if (wid < 2) {
            const uint32_t n = (wid == 0) ? cW : cL;
            uint32_t v = ((uint32_t)lane < n) ? (wid == 0 ? listW[lane] : listL[lane])
                                              : 0xFFFFFFFFu;
#pragma unroll
            for (int k = 2; k <= 32; k <<= 1) {
#pragma unroll
                for (int j = k >> 1; j > 0; j >>= 1) {
                    uint32_t o = __shfl_xor_sync(0xffffffffu, v, j);
                    bool up = ((lane & k) == 0);
                    bool lower = ((lane & j) == 0);
                    uint32_t mn = min(v, o), mx = max(v, o);
                    v = ((lower == up)) ? mn : mx;
                }
            }
            uint32_t rank = (wid == 0) ? rW : rL;   // 1-based, <= n <= 32
            uint32_t sel = __shfl_sync(0xffffffffu, v, (int)(rank - 1));
            if (lane == 0) pub[wid] = sel;
        }
        __syncthreads();
    } else {
        // ---- SLOW fallback: pass 3 (bits 17..8) + pass 4 (bits 7..0) ----
#pragma unroll
        for (int k = 0; k < EPT; k++) {
            uint32_t u = ur[k];
            if ((u >> 18) == pfxW14) atomicAdd(&hA[(u >> 8) & 0x3FFu], 1u);
            if ((u >> 18) == pfxL14) atomicAdd(&hB[(u >> 8) & 0x3FFu], 1u);
        }
        __syncthreads();
        {
            uint32_t ca[4], cb[4], sa = 0, sb = 0;
#pragma unroll
            for (int k = 0; k < 4; k++) {
                ca[k] = hA[tid * 4 + k]; hA[tid * 4 + k] = 0; sa += ca[k];
                cb[k] = hB[tid * 4 + k]; hB[tid * 4 + k] = 0; sb += cb[k];
            }
            unsigned long long e =
                block_exscan_u64((unsigned long long)sa | ((unsigned long long)sb << 32), stot);
            uint32_t ea = (uint32_t)e, eb = (uint32_t)(e >> 32);
            if (ea < rW && rW <= ea + sa) {
                uint32_t run = ea;
#pragma unroll
                for (int k = 0; k < 4; k++) {
                    if (rW > run && rW <= run + ca[k]) { pub[0] = tid * 4 + k; pub[1] = rW - run; }
                    run += ca[k];
                }
            }
            if (eb < rL && rL <= eb + sb) {
                uint32_t run = eb;
#pragma unroll
                for (int k = 0; k < 4; k++) {
                    if (rL > run && rL <= run + cb[k]) { pub[2] = tid * 4 + k; pub[3] = rL - run; }
                    run += cb[k];
                }
            }
            __syncthreads();
        }
        const uint32_t pfxW24 = (pfxW14 << 10) | pub[0]; rW = pub[1];
        const uint32_t pfxL24 = (pfxL14 << 10) | pub[2]; rL = pub[3];
        __syncthreads();
#pragma unroll
        for (int k = 0; k < EPT; k++) {
            uint32_t u = ur[k];
            if ((u >> 8) == pfxW24) atomicAdd(&hA[u & 0xFFu], 1u);
            if ((u >> 8) == pfxL24) atomicAdd(&hB[u & 0xFFu], 1u);
        }
        __syncthreads();
        {
            uint32_t sa = hA[tid]; hA[tid] = 0;
            uint32_t sb = hB[tid]; hB[tid] = 0;
            unsigned long long e =
                block_exscan_u64((unsigned long long)sa | ((unsigned long long)sb << 32), stot);
            uint32_t ea = (uint32_t)e, eb = (uint32_t)(e >> 32);
            if (ea < rW && rW <= ea + sa) pub[0] = (pfxW24 << 8) | (uint32_t)tid;
            if (eb < rL && rL <= eb + sb) pub[1] = (pfxL24 << 8) | (uint32_t)tid;
            __syncthreads();
        }
    }
    const uint32_t uw = pub[0];
    const uint32_t ul = pub[1];
    __syncthreads();

    const float sw_val = u2f(uw);
    const float sl_val = u2f(ul);

    // ---- branch-free counts + exp-sums ----
    unsigned long long packed = 0ull;
    float sW = 0.0f, sL = 0.0f;
#pragma unroll
    for (int k = 0; k < EPT; k++) {
        uint32_t u = ur[k];
        float s = u2f(u);
        float ew_f = __expf(s - maxF);
        float el_f = __expf(minF - s);
        bool gtW = (u > uw), eqW = (u == uw), ltL = (u < ul), eqL = (u == ul);
        sW += gtW ? ew_f : 0.0f;
        sL += ltL ? el_f : 0.0f;
        packed += (unsigned long long)gtW
                + ((unsigned long long)eqW << 16)
                + ((unsigned long long)ltL << 32)
                + ((unsigned long long)eqL << 48);
    }
    // fused block reduction: packed + sW + sL
#pragma unroll
    for (int o = 16; o; o >>= 1) {
        packed += __shfl_xor_sync(0xffffffffu, packed, o);
        sW += __shfl_xor_sync(0xffffffffu, sW, o);
        sL += __shfl_xor_sync(0xffffffffu, sL, o);
    }
    if (lane == 0) { sredu[wid] = packed; sredf[wid] = sW; sredf[8 + wid] = sL; }
    __syncthreads();
    if (tid < 32) {
        unsigned long long c = (lane < 8) ? sredu[lane] : 0ull;
        float a = (lane < 8) ? sredf[lane] : 0.0f;
        float b = (lane < 8) ? sredf[8 + lane] : 0.0f;
#pragma unroll
        for (int o = 4; o; o >>= 1) {
            c += __shfl_xor_sync(0xffffffffu, c, o);
            a += __shfl_xor_sync(0xffffffffu, a, o);
            b += __shfl_xor_sync(0xffffffffu, b, o);
        }
        if (lane == 0) { sredu[0] = c; sredf[0] = a; sredf[8] = b; }
    }
    __syncthreads();
    packed = sredu[0];
    sW = sredf[0];
    sL = sredf[8];

    const int nWgt = (int)(packed & 0xFFFFu);
    const int nWeq = (int)((packed >> 16) & 0xFFFFu);
    const int nLlt = (int)((packed >> 32) & 0xFFFFu);
    const int nLeq = (int)((packed >> 48) & 0xFFFFu);
    const int eWc = G - nWgt;   // equals-at-threshold to include (>=1)
    const int eLc = G - nLlt;

    const float expWeq = __expf(sw_val - maxF);
    const float expLeq = __expf(minF - sl_val);
    const float invW = 1.0f / (sW + (float)eWc * expWeq);
    const float invL = 1.0f / (sL + (float)eLc * expLeq);
    const float wEq = expWeq * invW;
    const float lEq = expLeq * invL;

    float4* outL = reinterpret_cast<float4*>(out + (size_t)row * S);
    float4* outSh = reinterpret_cast<float4*>(out + (size_t)BATCH * S + (size_t)row * S);

    if (nWeq == eWc && nLeq == eLc) {
        // ---- FAST write: branch-free selects ----
#pragma unroll
        for (int k = 0; k < 2; k++) {
            float lw[4], sw4[4];
#pragma unroll
            for (int c = 0; c < 4; c++) {
                uint32_t u = ur[k * 4 + c];
                float s = u2f(u);
                float ew_f = __expf(s - maxF);
                float el_f = __expf(minF - s);
                float lval = (u > uw) ? ew_f * invW : ((u == uw) ? wEq : 0.0f);
                float sval = (u < ul) ? el_f * invL : ((u == ul) ? lEq : 0.0f);
                lw[c] = lval;
                sw4[c] = sval;
            }
            outL[tid + k * NT]  = make_float4(lw[0], lw[1], lw[2], lw[3]);
            outSh[tid + k * NT] = make_float4(sw4[0], sw4[1], sw4[2], sw4[3]);
        }
    } else {
        // ---- RARE tie path: rank equals by global index (k, tid, c) via exscan ----
        uint32_t qW0 = 0, qW1 = 0, qL0 = 0, qL1 = 0;
#pragma unroll
        for (int c = 0; c < 4; c++) {
            qW0 += (ur[c] == uw);       qL0 += (ur[c] == ul);
            qW1 += (ur[4 + c] == uw);   qL1 += (ur[4 + c] == ul);
        }
        unsigned long long pk = (unsigned long long)qW0 | ((unsigned long long)qW1 << 16) |
                                ((unsigned long long)qL0 << 32) | ((unsigned long long)qL1 << 48);
        unsigned long long ex = block_exscan_u64(pk, stot);
        if (tid == NT - 1) sredu[7] = ex + pk;
        __syncthreads();
        unsigned long long tot = sredu[7];
        const uint32_t totW0 = (uint32_t)(tot & 0xFFFFull);
        const uint32_t totL0 = (uint32_t)((tot >> 32) & 0xFFFFull);
#pragma unroll
        for (int k = 0; k < 2; k++) {
            uint32_t beforeW = k ? totW0 + (uint32_t)((ex >> 16) & 0xFFFFull)
                                 : (uint32_t)(ex & 0xFFFFull);
            uint32_t beforeL = k ? totL0 + (uint32_t)((ex >> 48) & 0xFFFFull)
                                 : (uint32_t)((ex >> 32) & 0xFFFFull);
            float lw[4], sw4[4];
#pragma unroll
            for (int c = 0; c < 4; c++) {
                uint32_t u = ur[k * 4 + c];
                float s = u2f(u);
                float lval = 0.0f, sval = 0.0f;
                if (u > uw) lval = __expf(s - maxF) * invW;
                else if (u == uw) { lval = (beforeW < (uint32_t)eWc) ? wEq : 0.0f; beforeW++; }
                if (u < ul) sval = __expf(minF - s) * invL;
                else if (u == ul) { sval = (beforeL < (uint32_t)eLc) ? lEq : 0.0f; beforeL++; }
                lw[c] = lval;
                sw4[c] = sval;
            }
            outL[tid + k * NT]  = make_float4(lw[0], lw[1], lw[2], lw[3]);
            outSh[tid + k * NT] = make_float4(sw4[0], sw4[1], sw4[2], sw4[3]);
        }
    }

    // ---- short_ratio passthrough (clipped) ----
    if (tid == 0) {
        float r = short_ratio[row];
        r = fminf(fmaxf(r, 0.0f), 1.0f);
        out[(size_t)2 * BATCH * S + row] = r;
    }
}

extern "C" void kernel_launch(void* const* d_in, const int* in_sizes, int n_in,
                              void* d_out, int out_size) {
    const float* scores = (const float*)d_in[0];
    const float* ratio  = (const float*)d_in[1];
    // defensive: identify by size (scores is BATCH*S, ratio is BATCH)
    if (n_in >= 2 && in_sizes[0] == BATCH && in_sizes[1] == BATCH * S) {
        const float* t = scores; scores = ratio; ratio = t;
    }
    portfolio_kernel<<<BATCH, NT>>>(scores, ratio, (float*)d_out);
}

// round 6
// speedup vs baseline: 2.5829x; 1.4283x over previous
#include <cuda_runtime.h>
#include <cstdint>
#include <math_constants.h>

#define BATCH   16384
#define S       2048
#define G       256
#define NT      256
#define EPT     (S / NT)   // 8
#define LISTCAP 32
#define RANKW   1793u      // S-G+1 ascending
#define RANKL   256u       // G ascending

// ---- order-preserving float<->uint transforms (fallback path only) ----
__device__ __forceinline__ uint32_t f2u(float f) {
    uint32_t b = __float_as_uint(f);
    return b ^ ((b & 0x80000000u) ? 0xFFFFFFFFu : 0x80000000u);
}
__device__ __forceinline__ float u2f(uint32_t u) {
    uint32_t b = (u & 0x80000000u) ? (u ^ 0x80000000u) : ~u;
    return __uint_as_float(b);
}

// monotone value->bin map; MUST be used identically everywhere
__device__ __forceinline__ int val2bin(float s) {
    int b = __float2int_rd(fmaf(s, 128.0f, 512.0f));
    return min(max(b, 0), 1023);
}

// ---- block exclusive scan (u32), 256 threads ----
__device__ __forceinline__ uint32_t block_exscan_u32(uint32_t v, uint32_t* st) {
    const uint32_t full = 0xffffffffu;
    int lane = threadIdx.x & 31, w = threadIdx.x >> 5;
    uint32_t inc = v;
#pragma unroll
    for (int o = 1; o < 32; o <<= 1) {
        uint32_t t = __shfl_up_sync(full, inc, o);
        if (lane >= o) inc += t;
    }
    if (lane == 31) st[w] = inc;
    __syncthreads();
    if (threadIdx.x < 32) {
        uint32_t t = (lane < 8) ? st[lane] : 0u;
        uint32_t it = t;
#pragma unroll
        for (int o = 1; o < 8; o <<= 1) {
            uint32_t x = __shfl_up_sync(full, it, o);
            if (lane >= o) it += x;
        }
        if (lane < 8) st[lane] = it - t;
    }
    __syncthreads();
    uint32_t r = (inc - v) + st[w];
    __syncthreads();
    return r;
}

// ---- block exclusive scan (packed u64, independent 16-bit lanes) ----
__device__ __forceinline__ unsigned long long block_exscan_u64(unsigned long long v,
                                                               unsigned long long* st) {
    const uint32_t full = 0xffffffffu;
    int lane = threadIdx.x & 31, w = threadIdx.x >> 5;
    unsigned long long inc = v;
#pragma unroll
    for (int o = 1; o < 32; o <<= 1) {
        unsigned long long t = __shfl_up_sync(full, inc, o);
        if (lane >= o) inc += t;
    }
    if (lane == 31) st[w] = inc;
    __syncthreads();
    if (threadIdx.x < 32) {
        unsigned long long t = (lane < 8) ? st[lane] : 0ull;
        unsigned long long it = t;
#pragma unroll
        for (int o = 1; o < 8; o <<= 1) {
            unsigned long long x = __shfl_up_sync(full, it, o);
            if (lane >= o) it += x;
        }
        if (lane < 8) st[lane] = it - t;
    }
    __syncthreads();
    unsigned long long r = (inc - v) + st[w];
    __syncthreads();
    return r;
}

// ---- rare fallback: exact key radix select (11/11/10 bits), one rank ----
// All 256 threads must call (contains __syncthreads).
__device__ uint32_t radix_one(const uint32_t* uk, uint32_t rank,
                              uint32_t* hist, uint32_t* st, uint32_t* pub) {
    const int tid = threadIdx.x;
    uint32_t pfx = 0, r = rank;
#pragma unroll
    for (int rnd = 0; rnd < 3; rnd++) {
        // clear 2048 bins
        reinterpret_cast<uint4*>(hist)[tid] = make_uint4(0, 0, 0, 0);
        reinterpret_cast<uint4*>(hist)[NT + tid] = make_uint4(0, 0, 0, 0);
        __syncthreads();
#pragma unroll
        for (int k = 0; k < EPT; k++) {
            uint32_t u = uk[k];
            bool ok; uint32_t bin;
            if (rnd == 0)      { ok = true;                bin = u >> 21; }
            else if (rnd == 1) { ok = (u >> 21) == pfx;    bin = (u >> 10) & 0x7FFu; }
            else               { ok = (u >> 10) == pfx;    bin = u & 0x3FFu; }
            if (ok) atomicAdd(&hist[bin], 1u);
        }
        __syncthreads();
        const int nb = (rnd == 2) ? 4 : 8;
        uint32_t c[8], sum = 0;
#pragma unroll
        for (int k = 0; k < 8; k++) {
            c[k] = (k < nb) ? hist[tid * nb + k] : 0u;
            sum += c[k];
        }
        uint32_t exc = block_exscan_u32(sum, st);
        if (exc < r && r <= exc + sum) {
            uint32_t run = exc;
#pragma unroll
            for (int k = 0; k < 8; k++) {
                if (k < nb && r > run && r <= run + c[k]) {
                    pub[6] = tid * nb + k; pub[7] = r - run;
                }
                run += c[k];
            }
        }
        __syncthreads();
        uint32_t bin = pub[6]; r = pub[7];
        __syncthreads();
        pfx = (rnd == 2) ? ((pfx << 10) | bin) : ((pfx << 11) | bin);
    }
    return pfx;  // full 32-bit key
}

__global__ __launch_bounds__(NT, 6)
void portfolio_kernel(const float* __restrict__ scores,
                      const float* __restrict__ short_ratio,
                      float* __restrict__ out) {
    const int row = blockIdx.x;
    const int tid = threadIdx.x;
    const int lane = tid & 31;
    const int wid = tid >> 5;

    __shared__ __align__(16) uint32_t hist[2048];   // main: 1024 used; fallback: 2048
    __shared__ uint32_t st32[8];
    __shared__ unsigned long long st64[8];
    __shared__ float wmax[8], wmin[8];
    __shared__ uint32_t pub[8];
    __shared__ uint32_t cnt2[2];
    __shared__ float listW[LISTCAP], listL[LISTCAP];
    __shared__ float sredf[16];
    __shared__ unsigned long long sredu[8];

    // ---- load row (floats in registers), local max/min, clear histogram ----
    const float4* rowp = reinterpret_cast<const float4*>(scores + (size_t)row * S);
    float fr[8];
    float lmax = -CUDART_INF_F, lmin = CUDART_INF_F;
#pragma unroll
    for (int k = 0; k < 2; k++) {
        float4 v = rowp[tid + k * NT];
        fr[k * 4 + 0] = v.x; fr[k * 4 + 1] = v.y; fr[k * 4 + 2] = v.z; fr[k * 4 + 3] = v.w;
        lmax = fmaxf(lmax, fmaxf(fmaxf(v.x, v.y), fmaxf(v.z, v.w)));
        lmin = fminf(lmin, fminf(fminf(v.x, v.y), fminf(v.z, v.w)));
    }
    reinterpret_cast<uint4*>(hist)[tid] = make_uint4(0, 0, 0, 0);  // bins 0..1023
    if (tid < 2) cnt2[tid] = 0;
    // warp min/max
#pragma unroll
    for (int o = 16; o; o >>= 1) {
        lmax = fmaxf(lmax, __shfl_xor_sync(0xffffffffu, lmax, o));
        lmin = fminf(lmin, __shfl_xor_sync(0xffffffffu, lmin, o));
    }
    if (lane == 0) { wmax[wid] = lmax; wmin[wid] = lmin; }
    __syncthreads();

    // ---- single histogram pass (value-domain bins) ----
#pragma unroll
    for (int k = 0; k < EPT; k++) atomicAdd(&hist[val2bin(fr[k])], 1u);
    // meanwhile warp 0 finishes global min/max
    if (tid < 32) {
        float a = (lane < 8) ? wmax[lane] : -CUDART_INF_F;
        float b = (lane < 8) ? wmin[lane] : CUDART_INF_F;
#pragma unroll
        for (int o = 4; o; o >>= 1) {
            a = fmaxf(a, __shfl_xor_sync(0xffffffffu, a, o));
            b = fminf(b, __shfl_xor_sync(0xffffffffu, b, o));
        }
        if (lane == 0) { pub[4] = __float_as_uint(a); pub[5] = __float_as_uint(b); }
    }
    __syncthreads();
    const float maxF = __uint_as_float(pub[4]);
    const float minF = __uint_as_float(pub[5]);

    // ---- one scan locates BOTH ranks ----
    {
        uint4 v4 = reinterpret_cast<uint4*>(hist)[tid];
        uint32_t c[4] = {v4.x, v4.y, v4.z, v4.w};
        uint32_t sum = c[0] + c[1] + c[2] + c[3];
        uint32_t exc = block_exscan_u32(sum, st32);
        if (exc < RANKW && RANKW <= exc + sum) {
            uint32_t run = exc;
#pragma unroll
            for (int k = 0; k < 4; k++) {
                if (RANKW > run && RANKW <= run + c[k]) { pub[0] = tid * 4 + k; pub[1] = RANKW - run; }
                run += c[k];
            }
        }
        if (exc < RANKL && RANKL <= exc + sum) {
            uint32_t run = exc;
#pragma unroll
            for (int k = 0; k < 4; k++) {
                if (RANKL > run && RANKL <= run + c[k]) { pub[2] = tid * 4 + k; pub[3] = RANKL - run; }
                run += c[k];
            }
        }
        __syncthreads();
    }
    const uint32_t binW = pub[0]; const uint32_t rW = pub[1];
    const uint32_t binL = pub[2]; const uint32_t rL = pub[3];
    __syncthreads();

    // ---- capture crossing-bin members (expected ~3 each) ----
#pragma unroll
    for (int k = 0; k < EPT; k++) {
        float s = fr[k];
        uint32_t b = (uint32_t)val2bin(s);
        if (b == binW) {
            uint32_t i = atomicAdd(&cnt2[0], 1u);
            if (i < LISTCAP) listW[i] = s;
        }
        if (b == binL) {
            uint32_t i = atomicAdd(&cnt2[1], 1u);
            if (i < LISTCAP) listL[i] = s;
        }
    }
    __syncthreads();
    const uint32_t cW = cnt2[0], cL = cnt2[1];

    if (cW <= LISTCAP && cL <= LISTCAP) {
        // ---- FAST: warp 0 sorts listW, warp 1 sorts listL (bitonic, ascending) ----
        if (wid < 2) {
            const uint32_t n = (wid == 0) ? cW : cL;
            float v = ((uint32_t)lane < n) ? (wid == 0 ? listW[lane] : listL[lane])
                                           : CUDART_INF_F;
#pragma unroll
            for (int k = 2; k <= 32; k <<= 1) {
#pragma unroll
                for (int j = k >> 1; j > 0; j >>= 1) {
                    float o = __shfl_xor_sync(0xffffffffu, v, j);
                    bool up = ((lane & k) == 0);
                    bool lower = ((lane & j) == 0);
                    float mn = fminf(v, o), mx = fmaxf(v, o);
                    v = (lower == up) ? mn : mx;
                }
            }
            uint32_t rank = (wid == 0) ? rW : rL;   // 1-based
            float sel = __shfl_sync(0xffffffffu, v, (int)(rank - 1));
            if (lane == 0) pub[wid] = __float_as_uint(sel);
        }
        __syncthreads();
    } else {
        // ---- RARE fallback: exact full-key radix select, both thresholds ----
        uint32_t uk[8];
#pragma unroll
        for (int k = 0; k < EPT; k++) uk[k] = f2u(fr[k]);
        uint32_t kW = radix_one(uk, RANKW, hist, st32, pub);
        uint32_t kL = radix_one(uk, RANKL, hist, st32, pub);
        if (tid == 0) { pub[0] = __float_as_uint(u2f(kW)); pub[1] = __float_as_uint(u2f(kL)); }
        __syncthreads();
    }
    const float swv = __uint_as_float(pub[0]);
    const float slv = __uint_as_float(pub[1]);
    __syncthreads();

    // ---- counts + exp-sums (one expf per element; W/L strict sets disjoint) ----
    unsigned long long packed = 0ull;
    float sW = 0.0f, sL = 0.0f;
#pragma unroll
    for (int k = 0; k < EPT; k++) {
        float s = fr[k];
        bool gtW = (s > swv), eqW = (s == swv), ltL = (s < slv), eqL = (s == slv);
        float arg = gtW ? (s - maxF) : (minF - s);
        float e = __expf(arg);
        sW += gtW ? e : 0.0f;
        sL += ltL ? e : 0.0f;
        packed += (unsigned long long)gtW
                + ((unsigned long long)eqW << 16)
                + ((unsigned long long)ltL << 32)
                + ((unsigned long long)eqL << 48);
    }
    // fused block reduction: packed + sW + sL
#pragma unroll
    for (int o = 16; o; o >>= 1) {
        packed += __shfl_xor_sync(0xffffffffu, packed, o);
        sW += __shfl_xor_sync(0xffffffffu, sW, o);
        sL += __shfl_xor_sync(0xffffffffu, sL, o);
    }
    if (lane == 0) { sredu[wid] = packed; sredf[wid] = sW; sredf[8 + wid] = sL; }
    __syncthreads();
    if (tid < 32) {
        unsigned long long c = (lane < 8) ? sredu[lane] : 0ull;
        float a = (lane < 8) ? sredf[lane] : 0.0f;
        float b = (lane < 8) ? sredf[8 + lane] : 0.0f;
#pragma unroll
        for (int o = 4; o; o >>= 1) {
            c += __shfl_xor_sync(0xffffffffu, c, o);
            a += __shfl_xor_sync(0xffffffffu, a, o);
            b += __shfl_xor_sync(0xffffffffu, b, o);
        }
        if (lane == 0) { sredu[0] = c; sredf[0] = a; sredf[8] = b; }
    }
    __syncthreads();
    packed = sredu[0];
    sW = sredf[0];
    sL = sredf[8];

    const int nWgt = (int)(packed & 0xFFFFu);
    const int nWeq = (int)((packed >> 16) & 0xFFFFu);
    const int nLlt = (int)((packed >> 32) & 0xFFFFu);
    const int nLeq = (int)((packed >> 48) & 0xFFFFu);
    const int eWc = G - nWgt;
    const int eLc = G - nLlt;

    const float expWeq = __expf(swv - maxF);
    const float expLeq = __expf(minF - slv);
    const float invW = 1.0f / (sW + (float)eWc * expWeq);
    const float invL = 1.0f / (sL + (float)eLc * expLeq);
    const float wEq = expWeq * invW;
    const float lEq = expLeq * invL;

    float4* outL = reinterpret_cast<float4*>(out + (size_t)row * S);
    float4* outSh = reinterpret_cast<float4*>(out + (size_t)BATCH * S + (size_t)row * S);

    if (nWeq == eWc && nLeq == eLc) {
        // ---- FAST write: one expf per element, branch-free selects ----
#pragma unroll
        for (int k = 0; k < 2; k++) {
            float lw[4], sw4[4];
#pragma unroll
            for (int c = 0; c < 4; c++) {
                float s = fr[k * 4 + c];
                bool gtW = (s > swv), ltL = (s < slv);
                float arg = gtW ? (s - maxF) : (minF - s);
                float e = __expf(arg);
                lw[c]  = gtW ? e * invW : ((s == swv) ? wEq : 0.0f);
                sw4[c] = ltL ? e * invL : ((s == slv) ? lEq : 0.0f);
            }
            outL[tid + k * NT]  = make_float4(lw[0], lw[1], lw[2], lw[3]);
            outSh[tid + k * NT] = make_float4(sw4[0], sw4[1], sw4[2], sw4[3]);
        }
    } else {
        // ---- RARE tie path: rank equals by global index (k, tid, c) via exscan ----
        uint32_t qW0 = 0, qW1 = 0, qL0 = 0, qL1 = 0;
#pragma unroll
        for (int c = 0; c < 4; c++) {
            qW0 += (fr[c] == swv);       qL0 += (fr[c] == slv);
            qW1 += (fr[4 + c] == swv);   qL1 += (fr[4 + c] == slv);
        }
        unsigned long long pk = (unsigned long long)qW0 | ((unsigned long long)qW1 << 16) |
                                ((unsigned long long)qL0 << 32) | ((unsigned long long)qL1 << 48);
        unsigned long long ex = block_exscan_u64(pk, st64);
        if (tid == NT - 1) sredu[7] = ex + pk;
        __syncthreads();
        unsigned long long tot = sredu[7];
        const uint32_t totW0 = (uint32_t)(tot & 0xFFFFull);
        const uint32_t totL0 = (uint32_t)((tot >> 32) & 0xFFFFull);
#pragma unroll
        for (int k = 0; k < 2; k++) {
            uint32_t beforeW = k ? totW0 + (uint32_t)((ex >> 16) & 0xFFFFull)
                                 : (uint32_t)(ex & 0xFFFFull);
            uint32_t beforeL = k ? totL0 + (uint32_t)((ex >> 48) & 0xFFFFull)
                                 : (uint32_t)((ex >> 32) & 0xFFFFull);
            float lw[4], sw4[4];
#pragma unroll
            for (int c = 0; c < 4; c++) {
                float s = fr[k * 4 + c];
                float lval = 0.0f, sval = 0.0f;
                if (s > swv) lval = __expf(s - maxF) * invW;
                else if (s == swv) { lval = (beforeW < (uint32_t)eWc) ? wEq : 0.0f; beforeW++; }
                if (s < slv) sval = __expf(minF - s) * invL;
                else if (s == slv) { sval = (beforeL < (uint32_t)eLc) ? lEq : 0.0f; beforeL++; }
                lw[c] = lval;
                sw4[c] = sval;
            }
            outL[tid + k * NT]  = make_float4(lw[0], lw[1], lw[2], lw[3]);
            outSh[tid + k * NT] = make_float4(sw4[0], sw4[1], sw4[2], sw4[3]);
        }
    }

    // ---- short_ratio passthrough (clipped) ----
    if (tid == 0) {
        float r = short_ratio[row];
        r = fminf(fmaxf(r, 0.0f), 1.0f);
        out[(size_t)2 * BATCH * S + row] = r;
    }
}

extern "C" void kernel_launch(void* const* d_in, const int* in_sizes, int n_in,
                              void* d_out, int out_size) {
    const float* scores = (const float*)d_in[0];
    const float* ratio  = (const float*)d_in[1];
    if (n_in >= 2 && in_sizes[0] == BATCH && in_sizes[1] == BATCH * S) {
        const float* t = scores; scores = ratio; ratio = t;
    }
    portfolio_kernel<<<BATCH, NT>>>(scores, ratio, (float*)d_out);
}